// round 2
// baseline (speedup 1.0000x reference)
#include <cuda_runtime.h>

#define C_ 192
#define H_ 256
#define W_ 256
#define NH_ 8
#define HD_ 24
#define S_ 64
#define SCALE_ 0.20412414523193154f

// smem layout (floats)
#define XSH_STRIDE 193
#define QK_STRIDE 385
#define OFF_XSH 0
#define OFF_QK (64 * XSH_STRIDE)                 // 12352
#define OFF_WSH (OFF_QK + 64 * QK_STRIDE)        // +24640
#define OFF_WV (OFF_WSH + 2 * 16 * 384)          // +12288
#define OFF_VW (OFF_WV + C_ * NH_)               // +1536
#define OFF_G (OFF_VW + NH_ * S_)                // +512
#define OFF_B (OFF_G + C_)
#define SMEM_FLOATS (OFF_B + C_)
#define SMEM_BYTES (SMEM_FLOATS * 4)

__device__ float g_wveff[C_ * NH_];
__device__ float g_bveff[NH_];
__device__ float g_bpmean;

__global__ void precompute_kernel(const float* __restrict__ w_qkv,
                                  const float* __restrict__ b_qkv,
                                  const float* __restrict__ w_proj,
                                  const float* __restrict__ b_proj) {
  __shared__ float wps[C_];
  int k = threadIdx.x;  // 0..191
  float s = 0.f;
  for (int c = 0; c < C_; ++c) s += w_proj[k * C_ + c];
  wps[k] = s * (1.f / C_);
  __syncthreads();
  for (int h = 0; h < NH_; ++h) {
    float acc = 0.f;
    for (int d = 0; d < HD_; ++d)
      acc += w_qkv[k * (3 * C_) + 2 * C_ + h * HD_ + d] * wps[h * HD_ + d];
    g_wveff[k * NH_ + h] = acc;
  }
  if (k < NH_) {
    float acc = 0.f;
    for (int d = 0; d < HD_; ++d)
      acc += b_qkv[2 * C_ + k * HD_ + d] * wps[k * HD_ + d];
    g_bveff[k] = acc;
  }
  if (k == 0) {
    float acc = 0.f;
    for (int c = 0; c < C_; ++c) acc += b_proj[c];
    g_bpmean = acc * (1.f / C_);
  }
}

__global__ __launch_bounds__(256, 1) void swin_fused_kernel(
    const float* __restrict__ x, const float* __restrict__ gamma,
    const float* __restrict__ beta, const float* __restrict__ w_qkv,
    const float* __restrict__ b_qkv, float* __restrict__ out) {
  extern __shared__ float sm[];
  float* xsh = sm + OFF_XSH;    // [64][193] window tokens / xn
  float* qksh = sm + OFF_QK;    // [64][385] q (0..191) and k (192..383)
  float* wsh = sm + OFF_WSH;    // [2][16][384] weight tiles
  float* wvsh = sm + OFF_WV;    // [192][8] w_veff
  float* vwsh = sm + OFF_VW;    // [8][64] vw
  float* gsh = sm + OFF_G;      // gamma
  float* bsh = sm + OFF_B;      // beta

  const int tid = threadIdx.x;
  const int win = blockIdx.x;
  const int bN = win >> 10;
  const int wy = (win >> 5) & 31;
  const int wx = win & 31;
  const float* xbase =
      x + (size_t)bN * C_ * H_ * W_ + (size_t)(wy * 8) * W_ + wx * 8;

  for (int i = tid; i < C_; i += 256) {
    gsh[i] = gamma[i];
    bsh[i] = beta[i];
  }
  for (int i = tid; i < C_ * NH_; i += 256) wvsh[i] = g_wveff[i];

  // ---- load window: [B,C,H,W] -> xsh[s][c]
  #pragma unroll
  for (int u = 0; u < 48; ++u) {
    int idx = tid + u * 256;  // 0..12287
    int c = idx >> 6, s = idx & 63;
    xsh[s * XSH_STRIDE + c] =
        xbase[(size_t)c * (H_ * W_) + (s >> 3) * W_ + (s & 7)];
  }
  __syncthreads();

  // ---- LayerNorm over channel dim (warp: 8 tokens, 4 lanes/token)
  {
    int lane = tid & 31;
    int s = (tid >> 5) * 8 + (lane >> 2);
    int cl = lane & 3;
    float sum = 0.f, sq = 0.f;
    for (int c = cl; c < C_; c += 4) {
      float v = xsh[s * XSH_STRIDE + c];
      sum += v;
      sq += v * v;
    }
    sum += __shfl_xor_sync(0xffffffffu, sum, 1);
    sq += __shfl_xor_sync(0xffffffffu, sq, 1);
    sum += __shfl_xor_sync(0xffffffffu, sum, 2);
    sq += __shfl_xor_sync(0xffffffffu, sq, 2);
    float mu = sum * (1.f / C_);
    float rstd = rsqrtf(sq * (1.f / C_) - mu * mu + 1e-5f);
    for (int c = cl; c < C_; c += 4) {
      float v = xsh[s * XSH_STRIDE + c];
      xsh[s * XSH_STRIDE + c] = (v - mu) * rstd * gsh[c] + bsh[c];
    }
  }
  __syncthreads();

  // ---- Q/K GEMM: qksh[s][j] = xn[s][:] . w_qkv[:, j] + b_qkv[j], j in [0,384)
  {
    const int st = tid >> 5;  // token group 0..7 (tokens st*8..st*8+7)
    const int jt = tid & 31;  // column lane; cols jt + 32*jj
    float acc[8][12];
    #pragma unroll
    for (int i = 0; i < 8; ++i)
      #pragma unroll
      for (int j = 0; j < 12; ++j) acc[i][j] = 0.f;

    float4 pre[6];
    #pragma unroll
    for (int u = 0; u < 6; ++u) {
      int i4 = tid + u * 256;
      int r = i4 / 96, c4 = i4 % 96;
      pre[u] = *reinterpret_cast<const float4*>(w_qkv + (size_t)r * 576 + c4 * 4);
    }
    #pragma unroll
    for (int u = 0; u < 6; ++u) {
      int i4 = tid + u * 256;
      int r = i4 / 96, c4 = i4 % 96;
      *reinterpret_cast<float4*>(wsh + r * 384 + c4 * 4) = pre[u];
    }
    __syncthreads();

    for (int kt = 0; kt < 12; ++kt) {
      const int cur = kt & 1;
      if (kt < 11) {
        #pragma unroll
        for (int u = 0; u < 6; ++u) {
          int i4 = tid + u * 256;
          int r = i4 / 96, c4 = i4 % 96;
          pre[u] = *reinterpret_cast<const float4*>(
              w_qkv + (size_t)((kt + 1) * 16 + r) * 576 + c4 * 4);
        }
      }
      const float* wb = wsh + cur * 6144;
      const float* xb = xsh + st * 8 * XSH_STRIDE + kt * 16;
      #pragma unroll
      for (int kk = 0; kk < 16; ++kk) {
        float xv[8];
        #pragma unroll
        for (int i = 0; i < 8; ++i) xv[i] = xb[i * XSH_STRIDE + kk];
        float wv[12];
        #pragma unroll
        for (int j = 0; j < 12; ++j) wv[j] = wb[kk * 384 + jt + 32 * j];
        #pragma unroll
        for (int i = 0; i < 8; ++i)
          #pragma unroll
          for (int j = 0; j < 12; ++j) acc[i][j] = fmaf(xv[i], wv[j], acc[i][j]);
      }
      if (kt < 11) {
        #pragma unroll
        for (int u = 0; u < 6; ++u) {
          int i4 = tid + u * 256;
          int r = i4 / 96, c4 = i4 % 96;
          *reinterpret_cast<float4*>(wsh + (cur ^ 1) * 6144 + r * 384 + c4 * 4) =
              pre[u];
        }
        __syncthreads();
      }
    }

    #pragma unroll
    for (int j = 0; j < 12; ++j) {
      float bq = b_qkv[jt + 32 * j];
      #pragma unroll
      for (int i = 0; i < 8; ++i)
        qksh[(st * 8 + i) * QK_STRIDE + jt + 32 * j] = acc[i][j] + bq;
    }
  }
  __syncthreads();

  // ---- vw[h][t] = xn[t][:] . w_veff[:,h] + b_veff[h]
  {
    #pragma unroll
    for (int r = 0; r < 2; ++r) {
      int o = tid + r * 256;  // 0..511
      int s = o >> 3, h = o & 7;
      float acc = g_bveff[h];
      for (int c = 0; c < C_; ++c)
        acc = fmaf(xsh[s * XSH_STRIDE + c], wvsh[c * NH_ + h], acc);
      vwsh[h * S_ + s] = acc;
    }
  }
  __syncthreads();

  // ---- attention: logits + softmax + weighted vw sum, all in registers
  {
    const int tt = tid & 15;  // t lane; t = tt + 16*j
    const int ts = tid >> 4;  // s group; s = ts + 16*i
    float outAcc[4] = {0.f, 0.f, 0.f, 0.f};
    for (int h = 0; h < NH_; ++h) {
      float lacc[4][4];
      #pragma unroll
      for (int i = 0; i < 4; ++i)
        #pragma unroll
        for (int j = 0; j < 4; ++j) lacc[i][j] = 0.f;
      const float* qb = qksh + h * HD_;
      const float* kb = qksh + C_ + h * HD_;
      #pragma unroll
      for (int d = 0; d < HD_; ++d) {
        float qv[4], kv[4];
        #pragma unroll
        for (int i = 0; i < 4; ++i) qv[i] = qb[(ts + 16 * i) * QK_STRIDE + d];
        #pragma unroll
        for (int j = 0; j < 4; ++j) kv[j] = kb[(tt + 16 * j) * QK_STRIDE + d];
        #pragma unroll
        for (int i = 0; i < 4; ++i)
          #pragma unroll
          for (int j = 0; j < 4; ++j)
            lacc[i][j] = fmaf(qv[i], kv[j], lacc[i][j]);
      }
      #pragma unroll
      for (int i = 0; i < 4; ++i) {
        float m = fmaxf(fmaxf(lacc[i][0], lacc[i][1]),
                        fmaxf(lacc[i][2], lacc[i][3]));
        m = fmaxf(m, __shfl_xor_sync(0xffffffffu, m, 1, 16));
        m = fmaxf(m, __shfl_xor_sync(0xffffffffu, m, 2, 16));
        m = fmaxf(m, __shfl_xor_sync(0xffffffffu, m, 4, 16));
        m = fmaxf(m, __shfl_xor_sync(0xffffffffu, m, 8, 16));
        float sp = 0.f, spv = 0.f;
        #pragma unroll
        for (int j = 0; j < 4; ++j) {
          float p = __expf((lacc[i][j] - m) * SCALE_);
          sp += p;
          spv = fmaf(p, vwsh[h * S_ + tt + 16 * j], spv);
        }
        #pragma unroll
        for (int o = 1; o < 16; o <<= 1) {
          sp += __shfl_xor_sync(0xffffffffu, sp, o, 16);
          spv += __shfl_xor_sync(0xffffffffu, spv, o, 16);
        }
        outAcc[i] += spv / sp;
      }
    }
    if (tt == 0) {
      float bp = g_bpmean;
      #pragma unroll
      for (int i = 0; i < 4; ++i) {
        int s = ts + 16 * i;
        float v = outAcc[i] + bp;
        float sig = 1.f / (1.f + __expf(-v));
        out[(size_t)bN * (H_ * W_) + (size_t)(wy * 8 + (s >> 3)) * W_ + wx * 8 +
            (s & 7)] = sig;
      }
    }
  }
}

extern "C" void kernel_launch(void* const* d_in, const int* in_sizes, int n_in,
                              void* d_out, int out_size) {
  const float* x = (const float*)d_in[0];
  const float* gamma = (const float*)d_in[1];
  const float* beta = (const float*)d_in[2];
  const float* w_qkv = (const float*)d_in[3];
  const float* b_qkv = (const float*)d_in[4];
  const float* w_proj = (const float*)d_in[5];
  const float* b_proj = (const float*)d_in[6];
  float* out = (float*)d_out;

  cudaFuncSetAttribute(swin_fused_kernel,
                       cudaFuncAttributeMaxDynamicSharedMemorySize, SMEM_BYTES);

  precompute_kernel<<<1, C_>>>(w_qkv, b_qkv, w_proj, b_proj);
  swin_fused_kernel<<<8192, 256, SMEM_BYTES>>>(x, gamma, beta, w_qkv, b_qkv,
                                               out);
}

// round 4
// speedup vs baseline: 3.9044x; 3.9044x over previous
#include <cuda_runtime.h>
#include <cuda_bf16.h>

#define C_ 192
#define NH_ 8
#define HD_ 24
#define SCALE_ 0.20412414523193154f
#define CEXP_ 0.29448618f  // SCALE_ * log2(e)

// ---- smem float-index offsets ----
#define BIASf 0      // 392 floats: b_qkv[384] | bveff[8]
#define GAMMAf 392
#define BETAf 584
#define VWf 776      // [8][128] fp32
#define OUTPf 1800   // [16][64] fp32
// ---- byte offsets ----
#define OFF_ASH 11392             // bf16 A [128 rows][200] stride 400B = 51200
#define OFF_BCH 62592             // B chunk [392][48B] = 18816
#define OFF_ARENA 81408           // bf16 qk arena [128][408] stride 816B = 104448
#define STAGEf 20352              // fp32 stage_c [192][132] (overlaps arena)
#define SMEM_BYTES 185856

__device__ float g_wveff[C_ * NH_];
__device__ float g_bveff[NH_];
__device__ float g_bpmean;
__device__ uint4 g_wpack4[14112];  // [12 kt][392 n][48B]: bf16 frags, j<16 data

// ---------------- mma helpers ----------------
__device__ __forceinline__ void mma16(float* d, unsigned a0, unsigned a1,
                                      unsigned a2, unsigned a3, unsigned b0,
                                      unsigned b1) {
  asm volatile(
      "mma.sync.aligned.m16n8k16.row.col.f32.bf16.bf16.f32 "
      "{%0,%1,%2,%3},{%4,%5,%6,%7},{%8,%9},{%0,%1,%2,%3};"
      : "+f"(d[0]), "+f"(d[1]), "+f"(d[2]), "+f"(d[3])
      : "r"(a0), "r"(a1), "r"(a2), "r"(a3), "r"(b0), "r"(b1));
}
__device__ __forceinline__ void mma8(float* d, unsigned a0, unsigned a1,
                                     unsigned b0) {
  asm volatile(
      "mma.sync.aligned.m16n8k8.row.col.f32.bf16.bf16.f32 "
      "{%0,%1,%2,%3},{%4,%5},{%6},{%0,%1,%2,%3};"
      : "+f"(d[0]), "+f"(d[1]), "+f"(d[2]), "+f"(d[3])
      : "r"(a0), "r"(a1), "r"(b0));
}
__device__ __forceinline__ float ex2a(float x) {
  float r;
  asm("ex2.approx.f32 %0, %1;" : "=f"(r) : "f"(x));
  return r;
}
__device__ __forceinline__ unsigned pack_bf2(float hi, float lo) {
  unsigned r;
  asm("cvt.rn.bf16x2.f32 %0, %1, %2;" : "=r"(r) : "f"(hi), "f"(lo));
  return r;
}

// ---------------- precompute ----------------
__global__ void precompute1(const float* __restrict__ w_qkv,
                            const float* __restrict__ b_qkv,
                            const float* __restrict__ w_proj,
                            const float* __restrict__ b_proj) {
  __shared__ float wps[C_];
  int k = threadIdx.x;
  float s = 0.f;
  for (int c = 0; c < C_; ++c) s += w_proj[k * C_ + c];
  wps[k] = s * (1.f / C_);
  __syncthreads();
  for (int h = 0; h < NH_; ++h) {
    float acc = 0.f;
    for (int d = 0; d < HD_; ++d)
      acc += w_qkv[k * (3 * C_) + 2 * C_ + h * HD_ + d] * wps[h * HD_ + d];
    g_wveff[k * NH_ + h] = acc;
  }
  if (k < NH_) {
    float acc = 0.f;
    for (int d = 0; d < HD_; ++d)
      acc += b_qkv[2 * C_ + k * HD_ + d] * wps[k * HD_ + d];
    g_bveff[k] = acc;
  }
  if (k == 0) {
    float acc = 0.f;
    for (int c = 0; c < C_; ++c) acc += b_proj[c];
    g_bpmean = acc * (1.f / C_);
  }
}

// pack weights: g_wpack[kt][n][j<16] = w[k=kt*16+j][n] (n<384: w_qkv; else w_veff)
__global__ void precompute_pack(const float* __restrict__ w_qkv) {
  int idx = blockIdx.x * 256 + threadIdx.x;  // over 12*392*24
  if (idx >= 12 * 392 * 24) return;
  int j = idx % 24;
  int n = (idx / 24) % 392;
  int kt = idx / (24 * 392);
  float v = 0.f;
  if (j < 16) {
    int k = kt * 16 + j;
    v = (n < 384) ? w_qkv[k * 576 + n] : g_wveff[k * NH_ + (n - 384)];
  }
  reinterpret_cast<__nv_bfloat16*>(g_wpack4)[idx] = __float2bfloat16(v);
}

// ---------------- main fused kernel: 2 windows / CTA, 512 threads ----------
__global__ __launch_bounds__(512, 1) void swin_mma_kernel(
    const float* __restrict__ x, const float* __restrict__ gamma,
    const float* __restrict__ beta, const float* __restrict__ b_qkv,
    float* __restrict__ out) {
  extern __shared__ unsigned char smraw[];
  float* smf = reinterpret_cast<float*>(smraw);
  const int tid = threadIdx.x;
  const int wid = tid >> 5;
  const int lane = tid & 31;
  const int g = lane >> 2;  // group id
  const int t = lane & 3;   // thread-in-group

  const int win0 = blockIdx.x * 2;
  const int bN = win0 >> 10;
  const int wy = (win0 >> 5) & 31;
  const int wx0 = win0 & 31;
  const float* xb = x + (size_t)bN * (C_ * 65536) + wy * 2048 + wx0 * 8;

  if (tid < 392) smf[BIASf + tid] = (tid < 384) ? b_qkv[tid] : g_bveff[tid - 384];
  if (tid < C_) {
    smf[GAMMAf + tid] = gamma[tid];
    smf[BETAf + tid] = beta[tid];
  }

  // ---- load x -> stage_c [c][132] fp32 (coalesced float4)
  #pragma unroll
  for (int u = 0; u < 12; ++u) {
    int idx = tid + u * 512;  // 6144 float4
    int c = idx >> 5;
    int rem = idx & 31;
    int ty = rem >> 2, w2 = (rem >> 1) & 1, t4 = rem & 1;
    float4 v = *reinterpret_cast<const float4*>(xb + (size_t)c * 65536 +
                                                ty * 256 + w2 * 8 + t4 * 4);
    *reinterpret_cast<float4*>(smf + STAGEf + c * 132 + w2 * 64 + ty * 8 +
                               t4 * 4) = v;
  }
  __syncthreads();

  // ---- LayerNorm: thread (tok=tid>>2, cl=tid&3), write bf16 A tile
  {
    int tok = tid >> 2, cl = tid & 3;
    float vals[48];
    float sum = 0.f, sq = 0.f;
    #pragma unroll
    for (int i = 0; i < 48; ++i) {
      float v = smf[STAGEf + (cl + 4 * i) * 132 + tok];
      vals[i] = v;
      sum += v;
      sq += v * v;
    }
    sum += __shfl_xor_sync(0xffffffffu, sum, 1);
    sq += __shfl_xor_sync(0xffffffffu, sq, 1);
    sum += __shfl_xor_sync(0xffffffffu, sum, 2);
    sq += __shfl_xor_sync(0xffffffffu, sq, 2);
    float mu = sum * (1.f / C_);
    float rstd = rsqrtf(sq * (1.f / C_) - mu * mu + 1e-5f);
    #pragma unroll
    for (int i = 0; i < 48; ++i) {
      int c = cl + 4 * i;
      float xn = (vals[i] - mu) * rstd * smf[GAMMAf + c] + smf[BETAf + c];
      __nv_bfloat16 b = __float2bfloat16(xn);
      *reinterpret_cast<__nv_bfloat16*>(smraw + OFF_ASH + tok * 400 + c * 2) = b;
    }
  }

  // ---- QK+vw GEMM on HMMA: D[128][392], warp=(m-tile, n-half), 2 sub-passes
  {
    const int mt = wid & 7, nh = wid >> 3;
    uint4* bch4 = reinterpret_cast<uint4*>(smraw + OFF_BCH);
    #pragma unroll 1
    for (int pass = 0; pass < 2; ++pass) {
      const int ntBeg = (nh == 0) ? (pass ? 13 : 0) : (pass ? 37 : 25);
      const int ntN = (nh == 0 && pass == 0) ? 13 : 12;
      float acc[13][4];
      #pragma unroll
      for (int i = 0; i < 13; ++i)
        #pragma unroll
        for (int j = 0; j < 4; ++j) acc[i][j] = 0.f;

      #pragma unroll 1
      for (int kt = 0; kt < 12; ++kt) {
        __syncthreads();
        #pragma unroll
        for (int i = 0; i < 3; ++i) {
          int ii = tid + i * 512;
          if (ii < 1176) bch4[ii] = g_wpack4[kt * 1176 + ii];
        }
        __syncthreads();
        const unsigned char* ap =
            smraw + OFF_ASH + (mt * 16 + g) * 400 + kt * 32 + t * 4;
        unsigned a0 = *reinterpret_cast<const unsigned*>(ap);
        unsigned a1 = *reinterpret_cast<const unsigned*>(ap + 3200);
        unsigned a2 = *reinterpret_cast<const unsigned*>(ap + 16);
        unsigned a3 = *reinterpret_cast<const unsigned*>(ap + 3216);
        #pragma unroll
        for (int nt = 0; nt < 13; ++nt) {
          if (nt < ntN) {
            const unsigned char* bp =
                smraw + OFF_BCH + ((ntBeg + nt) * 8 + g) * 48 + t * 4;
            unsigned b0 = *reinterpret_cast<const unsigned*>(bp);
            unsigned b1 = *reinterpret_cast<const unsigned*>(bp + 16);
            mma16(acc[nt], a0, a1, a2, a3, b0, b1);
          }
        }
      }
      // epilogue
      #pragma unroll
      for (int nt = 0; nt < 13; ++nt) {
        if (nt < ntN) {
          int ntg = ntBeg + nt;
          int c0 = ntg * 8 + t * 2;
          int r0 = mt * 16 + g;
          if (ntg < 48) {
            float bx = smf[BIASf + c0], by = smf[BIASf + c0 + 1];
            unsigned p0 = pack_bf2(acc[nt][1] + by, acc[nt][0] + bx);
            unsigned p1 = pack_bf2(acc[nt][3] + by, acc[nt][2] + bx);
            *reinterpret_cast<unsigned*>(smraw + OFF_ARENA + r0 * 816 + c0 * 2) = p0;
            *reinterpret_cast<unsigned*>(smraw + OFF_ARENA + (r0 + 8) * 816 + c0 * 2) = p1;
          } else {
            int h0 = t * 2;
            float bv0 = smf[BIASf + 384 + h0], bv1 = smf[BIASf + 385 + h0];
            smf[VWf + h0 * 128 + r0] = acc[nt][0] + bv0;
            smf[VWf + (h0 + 1) * 128 + r0] = acc[nt][1] + bv1;
            smf[VWf + h0 * 128 + r0 + 8] = acc[nt][2] + bv0;
            smf[VWf + (h0 + 1) * 128 + r0 + 8] = acc[nt][3] + bv1;
          }
        }
      }
    }
  }
  __syncthreads();

  // ---- attention: warp = (window, head), HMMA logits + fragment softmax
  {
    const int win = wid >> 3, h = wid & 7;
    const int rbase = win * 64;
    const int kcol = (192 + h * HD_) * 2;  // byte offset of k head in row
    unsigned kb0[8], kb1[8], kb8[8];
    float2 vv[8];
    #pragma unroll
    for (int nt = 0; nt < 8; ++nt) {
      const unsigned char* rp = smraw + OFF_ARENA + (rbase + nt * 8 + g) * 816 + kcol + t * 4;
      kb0[nt] = *reinterpret_cast<const unsigned*>(rp);
      kb1[nt] = *reinterpret_cast<const unsigned*>(rp + 16);
      kb8[nt] = *reinterpret_cast<const unsigned*>(rp + 32);
      vv[nt] = *reinterpret_cast<const float2*>(smf + VWf + h * 128 + rbase + nt * 8 + t * 2);
    }
    #pragma unroll
    for (int mt2 = 0; mt2 < 4; ++mt2) {
      const unsigned char* qp =
          smraw + OFF_ARENA + (rbase + mt2 * 16 + g) * 816 + h * 48 + t * 4;
      unsigned a0 = *reinterpret_cast<const unsigned*>(qp);
      unsigned a1 = *reinterpret_cast<const unsigned*>(qp + 6528);  // +8 rows
      unsigned a2 = *reinterpret_cast<const unsigned*>(qp + 16);
      unsigned a3 = *reinterpret_cast<const unsigned*>(qp + 6544);
      unsigned aa0 = *reinterpret_cast<const unsigned*>(qp + 32);
      unsigned aa1 = *reinterpret_cast<const unsigned*>(qp + 6560);
      float acc[8][4];
      #pragma unroll
      for (int i = 0; i < 8; ++i)
        #pragma unroll
        for (int j = 0; j < 4; ++j) acc[i][j] = 0.f;
      #pragma unroll
      for (int nt = 0; nt < 8; ++nt) {
        mma16(acc[nt], a0, a1, a2, a3, kb0[nt], kb1[nt]);
        mma8(acc[nt], aa0, aa1, kb8[nt]);
      }
      // softmax rows g (acc[.][0..1]) and g+8 (acc[.][2..3])
      float m0 = -1e30f, m1 = -1e30f;
      #pragma unroll
      for (int nt = 0; nt < 8; ++nt) {
        m0 = fmaxf(m0, fmaxf(acc[nt][0], acc[nt][1]));
        m1 = fmaxf(m1, fmaxf(acc[nt][2], acc[nt][3]));
      }
      m0 = fmaxf(m0, __shfl_xor_sync(0xffffffffu, m0, 1));
      m1 = fmaxf(m1, __shfl_xor_sync(0xffffffffu, m1, 1));
      m0 = fmaxf(m0, __shfl_xor_sync(0xffffffffu, m0, 2));
      m1 = fmaxf(m1, __shfl_xor_sync(0xffffffffu, m1, 2));
      float mc0 = m0 * CEXP_, mc1 = m1 * CEXP_;
      float sp0 = 0.f, sv0 = 0.f, sp1 = 0.f, sv1 = 0.f;
      #pragma unroll
      for (int nt = 0; nt < 8; ++nt) {
        float p00 = ex2a(fmaf(acc[nt][0], CEXP_, -mc0));
        float p01 = ex2a(fmaf(acc[nt][1], CEXP_, -mc0));
        float p10 = ex2a(fmaf(acc[nt][2], CEXP_, -mc1));
        float p11 = ex2a(fmaf(acc[nt][3], CEXP_, -mc1));
        sp0 += p00 + p01;
        sp1 += p10 + p11;
        sv0 = fmaf(p00, vv[nt].x, fmaf(p01, vv[nt].y, sv0));
        sv1 = fmaf(p10, vv[nt].x, fmaf(p11, vv[nt].y, sv1));
      }
      sp0 += __shfl_xor_sync(0xffffffffu, sp0, 1);
      sv0 += __shfl_xor_sync(0xffffffffu, sv0, 1);
      sp1 += __shfl_xor_sync(0xffffffffu, sp1, 1);
      sv1 += __shfl_xor_sync(0xffffffffu, sv1, 1);
      sp0 += __shfl_xor_sync(0xffffffffu, sp0, 2);
      sv0 += __shfl_xor_sync(0xffffffffu, sv0, 2);
      sp1 += __shfl_xor_sync(0xffffffffu, sp1, 2);
      sv1 += __shfl_xor_sync(0xffffffffu, sv1, 2);
      if (t == 0) {
        smf[OUTPf + wid * 64 + mt2 * 16 + g] = __fdividef(sv0, sp0);
        smf[OUTPf + wid * 64 + mt2 * 16 + g + 8] = __fdividef(sv1, sp1);
      }
    }
  }
  __syncthreads();

  // ---- final: sum 8 heads, sigmoid, store
  if (tid < 128) {
    int w2 = tid >> 6, row = tid & 63;
    float s = 0.f;
    #pragma unroll
    for (int h = 0; h < 8; ++h) s += smf[OUTPf + (w2 * 8 + h) * 64 + row];
    float v = s + g_bpmean;
    float sig = 1.f / (1.f + __expf(-v));
    out[(size_t)bN * 65536 + (wy * 8 + (row >> 3)) * 256 + (wx0 + w2) * 8 +
        (row & 7)] = sig;
  }
}

extern "C" void kernel_launch(void* const* d_in, const int* in_sizes, int n_in,
                              void* d_out, int out_size) {
  const float* x = (const float*)d_in[0];
  const float* gamma = (const float*)d_in[1];
  const float* beta = (const float*)d_in[2];
  const float* w_qkv = (const float*)d_in[3];
  const float* b_qkv = (const float*)d_in[4];
  const float* w_proj = (const float*)d_in[5];
  const float* b_proj = (const float*)d_in[6];
  float* out = (float*)d_out;

  cudaFuncSetAttribute(swin_mma_kernel,
                       cudaFuncAttributeMaxDynamicSharedMemorySize, SMEM_BYTES);

  precompute1<<<1, C_>>>(w_qkv, b_qkv, w_proj, b_proj);
  precompute_pack<<<(12 * 392 * 24 + 255) / 256, 256>>>(w_qkv);
  swin_mma_kernel<<<4096, 512, SMEM_BYTES>>>(x, gamma, beta, b_qkv, out);
}

// round 5
// speedup vs baseline: 5.5772x; 1.4284x over previous
#include <cuda_runtime.h>
#include <cuda_bf16.h>
#include <cuda_fp16.h>

#define C_ 192
#define NH_ 8
#define HD_ 24
#define CEXP_ 0.29448618f  // (HD^-0.5) * log2(e)

// ---- smem float-index offsets (low region, 12224 bytes) ----
#define BIASf 0      // 392 floats: b_qkv[384] | bveff[8]
#define BIAS2f 392   // 192 u32: f16x2 bias pairs for q|k cols
#define GAMMAf 592
#define BETAf 784
#define VWf 976      // [8][132] fp32
#define OUTPf 2032   // [16][64] fp32
// ---- byte offsets ----
#define OFF_ASH 12224    // f16 A [128 rows][200] stride 400B = 51200
#define OFF_BCH 63424    // 3 x B chunk [400 n][48B] = 3*19200 = 57600
#define OFF_ARENA 121024 // f16 qk arena [128 rows][408] stride 816B = 104448
#define STAGEf 30256     // fp32 stage_c [192][132] (overlaps arena region)
#define SMEM_BYTES 225472

__device__ float g_wps[C_];
__device__ float g_wveff[C_ * NH_];
__device__ float g_bveff[NH_];
__device__ float g_bpmean;
__device__ uint4 g_wpack4[14400];  // [12 kt][400 n][48B] f16, j<16 real

// ---------------- asm helpers ----------------
__device__ __forceinline__ unsigned smem_u32(const void* p) {
  unsigned a;
  asm("{ .reg .u64 t; cvta.to.shared.u64 t, %1; cvt.u32.u64 %0, t; }"
      : "=r"(a) : "l"(p));
  return a;
}
__device__ __forceinline__ void cpasync16(unsigned dst, const void* src) {
  asm volatile("cp.async.cg.shared.global [%0], [%1], 16;" :: "r"(dst),
               "l"(src));
}
#define CP_COMMIT() asm volatile("cp.async.commit_group;" ::: "memory")
#define CP_WAIT(n) asm volatile("cp.async.wait_group %0;" :: "n"(n) : "memory")

// f16 inputs, f16 accum (QK+vw GEMM)
__device__ __forceinline__ void mma_h(unsigned* c, unsigned a0, unsigned a1,
                                      unsigned a2, unsigned a3, unsigned b0,
                                      unsigned b1) {
  asm volatile(
      "mma.sync.aligned.m16n8k16.row.col.f16.f16.f16.f16 "
      "{%0,%1},{%2,%3,%4,%5},{%6,%7},{%0,%1};"
      : "+r"(c[0]), "+r"(c[1])
      : "r"(a0), "r"(a1), "r"(a2), "r"(a3), "r"(b0), "r"(b1));
}
// f16 inputs, f32 accum (attention logits)
__device__ __forceinline__ void mma16f(float* d, unsigned a0, unsigned a1,
                                       unsigned a2, unsigned a3, unsigned b0,
                                       unsigned b1) {
  asm volatile(
      "mma.sync.aligned.m16n8k16.row.col.f32.f16.f16.f32 "
      "{%0,%1,%2,%3},{%4,%5,%6,%7},{%8,%9},{%0,%1,%2,%3};"
      : "+f"(d[0]), "+f"(d[1]), "+f"(d[2]), "+f"(d[3])
      : "r"(a0), "r"(a1), "r"(a2), "r"(a3), "r"(b0), "r"(b1));
}
__device__ __forceinline__ void mma8f(float* d, unsigned a0, unsigned a1,
                                      unsigned b0) {
  asm volatile(
      "mma.sync.aligned.m16n8k8.row.col.f32.f16.f16.f32 "
      "{%0,%1,%2,%3},{%4,%5},{%6},{%0,%1,%2,%3};"
      : "+f"(d[0]), "+f"(d[1]), "+f"(d[2]), "+f"(d[3])
      : "r"(a0), "r"(a1), "r"(b0));
}
__device__ __forceinline__ float ex2a(float x) {
  float r;
  asm("ex2.approx.f32 %0, %1;" : "=f"(r) : "f"(x));
  return r;
}
__device__ __forceinline__ unsigned pack_h2(float hi, float lo) {
  unsigned r;
  asm("cvt.rn.f16x2.f32 %0, %1, %2;" : "=r"(r) : "f"(hi), "f"(lo));
  return r;
}

// ---------------- precompute (all wide) ----------------
__global__ void pk_wps(const float* __restrict__ w_proj) {
  int k = blockIdx.x, l = threadIdx.x;  // 32 threads
  float s = 0.f;
  for (int c = l; c < C_; c += 32) s += w_proj[k * C_ + c];
  #pragma unroll
  for (int o = 16; o > 0; o >>= 1) s += __shfl_xor_sync(0xffffffffu, s, o);
  if (l == 0) g_wps[k] = s * (1.f / C_);
}

__global__ void pk_wv(const float* __restrict__ w_qkv,
                      const float* __restrict__ b_qkv,
                      const float* __restrict__ b_proj) {
  int idx = blockIdx.x * 256 + threadIdx.x;
  if (idx < 1536) {
    int k = idx >> 3, h = idx & 7;
    float a = 0.f;
    for (int d = 0; d < HD_; ++d)
      a += w_qkv[k * 576 + 384 + h * HD_ + d] * g_wps[h * HD_ + d];
    g_wveff[idx] = a;
  } else if (idx < 1544) {
    int h = idx - 1536;
    float a = 0.f;
    for (int d = 0; d < HD_; ++d)
      a += b_qkv[384 + h * HD_ + d] * g_wps[h * HD_ + d];
    g_bveff[h] = a;
  } else if (idx == 1544) {
    float a = 0.f;
    for (int c = 0; c < C_; ++c) a += b_proj[c];
    g_bpmean = a * (1.f / C_);
  }
}

__global__ void pk_pack(const float* __restrict__ w_qkv) {
  int idx = blockIdx.x * 256 + threadIdx.x;  // 12*400*24 = 115200
  if (idx >= 115200) return;
  int j = idx % 24;
  int n = (idx / 24) % 400;
  int kt = idx / 9600;
  float v = 0.f;
  if (j < 16 && n < 392) {
    int k = kt * 16 + j;
    v = (n < 384) ? w_qkv[k * 576 + n] : g_wveff[k * 8 + (n - 384)];
  }
  reinterpret_cast<__half*>(g_wpack4)[idx] = __float2half(v);
}

// ---------------- main fused kernel: 2 windows / CTA, 512 threads ----------
__global__ __launch_bounds__(512, 1) void swin_mma_kernel(
    const float* __restrict__ x, const float* __restrict__ gamma,
    const float* __restrict__ beta, const float* __restrict__ b_qkv,
    float* __restrict__ out) {
  extern __shared__ unsigned char smraw[];
  float* smf = reinterpret_cast<float*>(smraw);
  unsigned* smu = reinterpret_cast<unsigned*>(smraw);
  const unsigned sbase = smem_u32(smraw);
  const int tid = threadIdx.x;
  const int wid = tid >> 5;
  const int lane = tid & 31;
  const int g = lane >> 2;
  const int t = lane & 3;

  const int win0 = blockIdx.x * 2;
  const int bN = win0 >> 10;
  const int wy = (win0 >> 5) & 31;
  const int wx0 = win0 & 31;
  const float* xb = x + (size_t)bN * (C_ * 65536) + wy * 2048 + wx0 * 8;

  if (tid < 392)
    smf[BIASf + tid] = (tid < 384) ? b_qkv[tid] : g_bveff[tid - 384];
  if (tid < C_) {
    smf[GAMMAf + tid] = gamma[tid];
    smf[BETAf + tid] = beta[tid];
  }

  // ---- load x -> stage_c [c][132] fp32 (coalesced float4)
  #pragma unroll
  for (int u = 0; u < 12; ++u) {
    int idx = tid + u * 512;  // 6144 float4
    int c = idx >> 5;
    int rem = idx & 31;
    int ty = rem >> 2, w2 = (rem >> 1) & 1, t4 = rem & 1;
    float4 v = *reinterpret_cast<const float4*>(xb + (size_t)c * 65536 +
                                                ty * 256 + w2 * 8 + t4 * 4);
    *reinterpret_cast<float4*>(smf + STAGEf + c * 132 + w2 * 64 + ty * 8 +
                               t4 * 4) = v;
  }
  __syncthreads();

  // bias f16x2 pairs for q|k cols (after biasf visible)
  if (tid < 192) smu[BIAS2f + tid] = pack_h2(smf[BIASf + 2 * tid + 1],
                                             smf[BIASf + 2 * tid]);

  // ---- LayerNorm: thread (tok=tid>>2, cl2=tid&3), write f16 A tile (paired)
  {
    int tok = tid >> 2, cl2 = tid & 3;
    float v0a[24], v1a[24];
    float sum = 0.f, sq = 0.f;
    #pragma unroll
    for (int i = 0; i < 24; ++i) {
      int c = 8 * i + 2 * cl2;
      float v0 = smf[STAGEf + c * 132 + tok];
      float v1 = smf[STAGEf + (c + 1) * 132 + tok];
      v0a[i] = v0;
      v1a[i] = v1;
      sum += v0 + v1;
      sq += v0 * v0 + v1 * v1;
    }
    sum += __shfl_xor_sync(0xffffffffu, sum, 1);
    sq += __shfl_xor_sync(0xffffffffu, sq, 1);
    sum += __shfl_xor_sync(0xffffffffu, sum, 2);
    sq += __shfl_xor_sync(0xffffffffu, sq, 2);
    float mu = sum * (1.f / C_);
    float rstd = rsqrtf(sq * (1.f / C_) - mu * mu + 1e-5f);
    #pragma unroll
    for (int i = 0; i < 24; ++i) {
      int c = 8 * i + 2 * cl2;
      float xn0 = (v0a[i] - mu) * rstd * smf[GAMMAf + c] + smf[BETAf + c];
      float xn1 =
          (v1a[i] - mu) * rstd * smf[GAMMAf + c + 1] + smf[BETAf + c + 1];
      *reinterpret_cast<unsigned*>(smraw + OFF_ASH + tok * 400 + c * 2) =
          pack_h2(xn1, xn0);
    }
  }

  // ---- QK+vw GEMM: D[128][392(+pad)] = A[128x192] * W, f16 accum, 1 pass
  {
    const int mt = wid & 7, nh = wid >> 3;
    const int ntBeg = nh * 25;
    unsigned acc[25][2];
    #pragma unroll
    for (int i = 0; i < 25; ++i) acc[i][0] = acc[i][1] = 0u;

    // prefetch chunks 0,1
    #pragma unroll
    for (int p = 0; p < 2; ++p) {
      unsigned db = sbase + OFF_BCH + p * 19200;
      const uint4* src = g_wpack4 + p * 1200;
      for (int i = tid; i < 1200; i += 512) cpasync16(db + i * 16, src + i);
      CP_COMMIT();
    }

    #pragma unroll 1
    for (int kt = 0; kt < 12; ++kt) {
      if (kt < 11) CP_WAIT(1); else CP_WAIT(0);
      __syncthreads();
      if (kt + 2 < 12) {
        int s2 = (kt + 2) % 3;
        unsigned db = sbase + OFF_BCH + s2 * 19200;
        const uint4* src = g_wpack4 + (kt + 2) * 1200;
        for (int i = tid; i < 1200; i += 512) cpasync16(db + i * 16, src + i);
        CP_COMMIT();
      }
      const unsigned char* ap =
          smraw + OFF_ASH + (mt * 16 + g) * 400 + kt * 32 + t * 4;
      unsigned a0 = *reinterpret_cast<const unsigned*>(ap);
      unsigned a1 = *reinterpret_cast<const unsigned*>(ap + 3200);
      unsigned a2 = *reinterpret_cast<const unsigned*>(ap + 16);
      unsigned a3 = *reinterpret_cast<const unsigned*>(ap + 3216);
      const unsigned char* bbase = smraw + OFF_BCH + (kt % 3) * 19200;
      #pragma unroll
      for (int nt = 0; nt < 25; ++nt) {
        const unsigned char* bp = bbase + ((ntBeg + nt) * 8 + g) * 48 + t * 4;
        unsigned b0 = *reinterpret_cast<const unsigned*>(bp);
        unsigned b1 = *reinterpret_cast<const unsigned*>(bp + 16);
        mma_h(acc[nt], a0, a1, a2, a3, b0, b1);
      }
    }

    // epilogue
    const int r0 = mt * 16 + g;
    #pragma unroll
    for (int nt = 0; nt < 25; ++nt) {
      int ntg = ntBeg + nt;
      if (ntg < 48) {
        __half2 bp2 = *reinterpret_cast<__half2*>(smu + BIAS2f + ntg * 4 + t);
        __half2 p0 = __hadd2(*reinterpret_cast<__half2*>(&acc[nt][0]), bp2);
        __half2 p1 = __hadd2(*reinterpret_cast<__half2*>(&acc[nt][1]), bp2);
        int cb = (ntg * 8 + 2 * t) * 2;
        *reinterpret_cast<__half2*>(smraw + OFF_ARENA + r0 * 816 + cb) = p0;
        *reinterpret_cast<__half2*>(smraw + OFF_ARENA + (r0 + 8) * 816 + cb) =
            p1;
      } else if (ntg == 48) {
        float2 v0 = __half22float2(*reinterpret_cast<__half2*>(&acc[nt][0]));
        float2 v1 = __half22float2(*reinterpret_cast<__half2*>(&acc[nt][1]));
        int h0 = 2 * t;
        float bv0 = smf[BIASf + 384 + h0], bv1 = smf[BIASf + 385 + h0];
        smf[VWf + h0 * 132 + r0] = v0.x + bv0;
        smf[VWf + (h0 + 1) * 132 + r0] = v0.y + bv1;
        smf[VWf + h0 * 132 + r0 + 8] = v1.x + bv0;
        smf[VWf + (h0 + 1) * 132 + r0 + 8] = v1.y + bv1;
      }
    }
  }
  __syncthreads();

  // ---- attention: warp = (window, head), HMMA logits + fragment softmax
  {
    const int h = wid & 7;
    const int rbase = (wid >> 3) * 64;
    const int kcol = (192 + h * HD_) * 2;
    unsigned kb0[8], kb1[8], kb8[8];
    float2 vv[8];
    #pragma unroll
    for (int nt = 0; nt < 8; ++nt) {
      const unsigned char* rp =
          smraw + OFF_ARENA + (rbase + nt * 8 + g) * 816 + kcol + t * 4;
      kb0[nt] = *reinterpret_cast<const unsigned*>(rp);
      kb1[nt] = *reinterpret_cast<const unsigned*>(rp + 16);
      kb8[nt] = *reinterpret_cast<const unsigned*>(rp + 32);
      vv[nt] = *reinterpret_cast<const float2*>(smf + VWf + h * 132 + rbase +
                                                nt * 8 + t * 2);
    }
    #pragma unroll
    for (int mt2 = 0; mt2 < 4; ++mt2) {
      const unsigned char* qp =
          smraw + OFF_ARENA + (rbase + mt2 * 16 + g) * 816 + h * 48 + t * 4;
      unsigned a0 = *reinterpret_cast<const unsigned*>(qp);
      unsigned a1 = *reinterpret_cast<const unsigned*>(qp + 6528);
      unsigned a2 = *reinterpret_cast<const unsigned*>(qp + 16);
      unsigned a3 = *reinterpret_cast<const unsigned*>(qp + 6544);
      unsigned aa0 = *reinterpret_cast<const unsigned*>(qp + 32);
      unsigned aa1 = *reinterpret_cast<const unsigned*>(qp + 6560);
      float acc[8][4];
      #pragma unroll
      for (int i = 0; i < 8; ++i)
        #pragma unroll
        for (int j = 0; j < 4; ++j) acc[i][j] = 0.f;
      #pragma unroll
      for (int nt = 0; nt < 8; ++nt) {
        mma16f(acc[nt], a0, a1, a2, a3, kb0[nt], kb1[nt]);
        mma8f(acc[nt], aa0, aa1, kb8[nt]);
      }
      float m0 = -1e30f, m1 = -1e30f;
      #pragma unroll
      for (int nt = 0; nt < 8; ++nt) {
        m0 = fmaxf(m0, fmaxf(acc[nt][0], acc[nt][1]));
        m1 = fmaxf(m1, fmaxf(acc[nt][2], acc[nt][3]));
      }
      m0 = fmaxf(m0, __shfl_xor_sync(0xffffffffu, m0, 1));
      m1 = fmaxf(m1, __shfl_xor_sync(0xffffffffu, m1, 1));
      m0 = fmaxf(m0, __shfl_xor_sync(0xffffffffu, m0, 2));
      m1 = fmaxf(m1, __shfl_xor_sync(0xffffffffu, m1, 2));
      float mc0 = m0 * CEXP_, mc1 = m1 * CEXP_;
      float sp0 = 0.f, sv0 = 0.f, sp1 = 0.f, sv1 = 0.f;
      #pragma unroll
      for (int nt = 0; nt < 8; ++nt) {
        float p00 = ex2a(fmaf(acc[nt][0], CEXP_, -mc0));
        float p01 = ex2a(fmaf(acc[nt][1], CEXP_, -mc0));
        float p10 = ex2a(fmaf(acc[nt][2], CEXP_, -mc1));
        float p11 = ex2a(fmaf(acc[nt][3], CEXP_, -mc1));
        sp0 += p00 + p01;
        sp1 += p10 + p11;
        sv0 = fmaf(p00, vv[nt].x, fmaf(p01, vv[nt].y, sv0));
        sv1 = fmaf(p10, vv[nt].x, fmaf(p11, vv[nt].y, sv1));
      }
      sp0 += __shfl_xor_sync(0xffffffffu, sp0, 1);
      sv0 += __shfl_xor_sync(0xffffffffu, sv0, 1);
      sp1 += __shfl_xor_sync(0xffffffffu, sp1, 1);
      sv1 += __shfl_xor_sync(0xffffffffu, sv1, 1);
      sp0 += __shfl_xor_sync(0xffffffffu, sp0, 2);
      sv0 += __shfl_xor_sync(0xffffffffu, sv0, 2);
      sp1 += __shfl_xor_sync(0xffffffffu, sp1, 2);
      sv1 += __shfl_xor_sync(0xffffffffu, sv1, 2);
      if (t == 0) {
        smf[OUTPf + wid * 64 + mt2 * 16 + g] = __fdividef(sv0, sp0);
        smf[OUTPf + wid * 64 + mt2 * 16 + g + 8] = __fdividef(sv1, sp1);
      }
    }
  }
  __syncthreads();

  // ---- final: sum 8 heads, sigmoid, store
  if (tid < 128) {
    int w2 = tid >> 6, row = tid & 63;
    float s = 0.f;
    #pragma unroll
    for (int h = 0; h < 8; ++h) s += smf[OUTPf + (w2 * 8 + h) * 64 + row];
    float v = s + g_bpmean;
    float sig = 1.f / (1.f + __expf(-v));
    out[(size_t)bN * 65536 + (wy * 8 + (row >> 3)) * 256 + (wx0 + w2) * 8 +
        (row & 7)] = sig;
  }
}

extern "C" void kernel_launch(void* const* d_in, const int* in_sizes, int n_in,
                              void* d_out, int out_size) {
  const float* x = (const float*)d_in[0];
  const float* gamma = (const float*)d_in[1];
  const float* beta = (const float*)d_in[2];
  const float* w_qkv = (const float*)d_in[3];
  const float* b_qkv = (const float*)d_in[4];
  const float* w_proj = (const float*)d_in[5];
  const float* b_proj = (const float*)d_in[6];
  float* out = (float*)d_out;

  cudaFuncSetAttribute(swin_mma_kernel,
                       cudaFuncAttributeMaxDynamicSharedMemorySize, SMEM_BYTES);

  pk_wps<<<C_, 32>>>(w_proj);
  pk_wv<<<7, 256>>>(w_qkv, b_qkv, b_proj);
  pk_pack<<<(115200 + 255) / 256, 256>>>(w_qkv);
  swin_mma_kernel<<<4096, 512, SMEM_BYTES>>>(x, gamma, beta, b_qkv, out);
}

// round 6
// speedup vs baseline: 5.6183x; 1.0074x over previous
#include <cuda_runtime.h>
#include <cuda_fp16.h>

#define C_ 192
#define NH_ 8
#define HD_ 24
#define CEXP_ 0.29448618f  // (HD^-0.5) * log2(e)

// ---- smem float-index offsets (low region, 12224 bytes) ----
#define BIASf 0      // 392 floats: b_qkv[384] | bveff[8]
#define BIAS2f 392   // 192 u32: f16x2 bias pairs
#define GAMMAf 592
#define BETAf 784
#define VWf 976      // [8][132] fp32
#define OUTPf 2032   // [16][64] fp32
// ---- byte offsets ----
#define OFF_ASH 12224     // f16 A [128 rows][200] stride 400B = 51200
#define OFF_BCH 63424     // 2 x B chunk [448 n][48B] = 2*21504 = 43008
#define CHUNKB 21504
#define OFF_ARENA 106432  // f16 qk arena [128 rows][408] stride 816B = 104448
#define STAGEf 26608      // fp32 stage_c [192][132] (overlaps arena region)
#define SMEM_BYTES 210880

__device__ float g_wps[C_];
__device__ float g_wveff[C_ * NH_];
__device__ float g_bveff[NH_];
__device__ float g_bpmean;
__device__ uint4 g_wpack4[16128];  // [12 kt][448 n][48B] f16, n<392 & j<16 real

// ---------------- asm helpers ----------------
__device__ __forceinline__ unsigned smem_u32(const void* p) {
  unsigned a;
  asm("{ .reg .u64 t; cvta.to.shared.u64 t, %1; cvt.u32.u64 %0, t; }"
      : "=r"(a) : "l"(p));
  return a;
}
__device__ __forceinline__ void cpasync16(unsigned dst, const void* src) {
  asm volatile("cp.async.cg.shared.global [%0], [%1], 16;" :: "r"(dst),
               "l"(src));
}
#define CP_COMMIT() asm volatile("cp.async.commit_group;" ::: "memory")
#define CP_WAIT0() asm volatile("cp.async.wait_group 0;" ::: "memory")

__device__ __forceinline__ void ldsm4(unsigned* r, unsigned addr) {
  asm volatile("ldmatrix.sync.aligned.m8n8.x4.shared.b16 {%0,%1,%2,%3}, [%4];"
               : "=r"(r[0]), "=r"(r[1]), "=r"(r[2]), "=r"(r[3]) : "r"(addr));
}
__device__ __forceinline__ void ldsm2(unsigned* r, unsigned addr) {
  asm volatile("ldmatrix.sync.aligned.m8n8.x2.shared.b16 {%0,%1}, [%2];"
               : "=r"(r[0]), "=r"(r[1]) : "r"(addr));
}
// f16 in, f16 accum (projection GEMM)
__device__ __forceinline__ void mma_h(unsigned* c, unsigned a0, unsigned a1,
                                      unsigned a2, unsigned a3, unsigned b0,
                                      unsigned b1) {
  asm volatile(
      "mma.sync.aligned.m16n8k16.row.col.f16.f16.f16.f16 "
      "{%0,%1},{%2,%3,%4,%5},{%6,%7},{%0,%1};"
      : "+r"(c[0]), "+r"(c[1])
      : "r"(a0), "r"(a1), "r"(a2), "r"(a3), "r"(b0), "r"(b1));
}
// f16 in, f32 accum (attention logits)
__device__ __forceinline__ void mma16f(float* d, unsigned a0, unsigned a1,
                                       unsigned a2, unsigned a3, unsigned b0,
                                       unsigned b1) {
  asm volatile(
      "mma.sync.aligned.m16n8k16.row.col.f32.f16.f16.f32 "
      "{%0,%1,%2,%3},{%4,%5,%6,%7},{%8,%9},{%0,%1,%2,%3};"
      : "+f"(d[0]), "+f"(d[1]), "+f"(d[2]), "+f"(d[3])
      : "r"(a0), "r"(a1), "r"(a2), "r"(a3), "r"(b0), "r"(b1));
}
__device__ __forceinline__ void mma8f(float* d, unsigned a0, unsigned a1,
                                      unsigned b0) {
  asm volatile(
      "mma.sync.aligned.m16n8k8.row.col.f32.f16.f16.f32 "
      "{%0,%1,%2,%3},{%4,%5},{%6},{%0,%1,%2,%3};"
      : "+f"(d[0]), "+f"(d[1]), "+f"(d[2]), "+f"(d[3])
      : "r"(a0), "r"(a1), "r"(b0));
}
__device__ __forceinline__ float ex2a(float x) {
  float r;
  asm("ex2.approx.f32 %0, %1;" : "=f"(r) : "f"(x));
  return r;
}
__device__ __forceinline__ unsigned pack_h2(float hi, float lo) {
  unsigned r;
  asm("cvt.rn.f16x2.f32 %0, %1, %2;" : "=r"(r) : "f"(hi), "f"(lo));
  return r;
}

// ---------------- precompute (all wide) ----------------
__global__ void pk_wps(const float* __restrict__ w_proj) {
  int k = blockIdx.x, l = threadIdx.x;
  float s = 0.f;
  for (int c = l; c < C_; c += 32) s += w_proj[k * C_ + c];
  #pragma unroll
  for (int o = 16; o > 0; o >>= 1) s += __shfl_xor_sync(0xffffffffu, s, o);
  if (l == 0) g_wps[k] = s * (1.f / C_);
}

__global__ void pk_wv(const float* __restrict__ w_qkv,
                      const float* __restrict__ b_qkv,
                      const float* __restrict__ b_proj) {
  int idx = blockIdx.x * 256 + threadIdx.x;
  if (idx < 1536) {
    int k = idx >> 3, h = idx & 7;
    float a = 0.f;
    for (int d = 0; d < HD_; ++d)
      a += w_qkv[k * 576 + 384 + h * HD_ + d] * g_wps[h * HD_ + d];
    g_wveff[idx] = a;
  } else if (idx < 1544) {
    int h = idx - 1536;
    float a = 0.f;
    for (int d = 0; d < HD_; ++d)
      a += b_qkv[384 + h * HD_ + d] * g_wps[h * HD_ + d];
    g_bveff[h] = a;
  } else if (idx == 1544) {
    float a = 0.f;
    for (int c = 0; c < C_; ++c) a += b_proj[c];
    g_bpmean = a * (1.f / C_);
  }
}

__global__ void pk_pack(const float* __restrict__ w_qkv) {
  int idx = blockIdx.x * 256 + threadIdx.x;  // 12*448*24 = 129024
  if (idx >= 129024) return;
  int j = idx % 24;
  int n = (idx / 24) % 448;
  int kt = idx / 10752;
  float v = 0.f;
  if (j < 16 && n < 392) {
    int k = kt * 16 + j;
    v = (n < 384) ? w_qkv[k * 576 + n] : g_wveff[k * 8 + (n - 384)];
  }
  reinterpret_cast<__half*>(g_wpack4)[idx] = __float2half(v);
}

// ---------------- main fused kernel: 2 windows / CTA, 512 threads ----------
__global__ __launch_bounds__(512, 1) void swin_mma_kernel(
    const float* __restrict__ x, const float* __restrict__ gamma,
    const float* __restrict__ beta, const float* __restrict__ b_qkv,
    float* __restrict__ out) {
  extern __shared__ unsigned char smraw[];
  float* smf = reinterpret_cast<float*>(smraw);
  unsigned* smu = reinterpret_cast<unsigned*>(smraw);
  const unsigned sbase = smem_u32(smraw);
  const int tid = threadIdx.x;
  const int wid = tid >> 5;
  const int lane = tid & 31;
  const int g = lane >> 2;
  const int t = lane & 3;

  const int win0 = blockIdx.x * 2;
  const int bN = win0 >> 10;
  const int wy = (win0 >> 5) & 31;
  const int wx0 = win0 & 31;
  const float* xb = x + (size_t)bN * (C_ * 65536) + wy * 2048 + wx0 * 8;

  // prefetch B chunk 0 (overlaps x-load + LN)
  {
    unsigned db = sbase + OFF_BCH;
    for (int i = tid; i < 1344; i += 512) cpasync16(db + i * 16, g_wpack4 + i);
    CP_COMMIT();
  }

  if (tid < 392)
    smf[BIASf + tid] = (tid < 384) ? b_qkv[tid] : g_bveff[tid - 384];
  if (tid < C_) {
    smf[GAMMAf + tid] = gamma[tid];
    smf[BETAf + tid] = beta[tid];
  }

  // ---- load x -> stage_c [c][132] fp32 (coalesced float4)
  #pragma unroll
  for (int u = 0; u < 12; ++u) {
    int idx = tid + u * 512;
    int c = idx >> 5;
    int rem = idx & 31;
    int ty = rem >> 2, w2 = (rem >> 1) & 1, t4 = rem & 1;
    float4 v = *reinterpret_cast<const float4*>(xb + (size_t)c * 65536 +
                                                ty * 256 + w2 * 8 + t4 * 4);
    *reinterpret_cast<float4*>(smf + STAGEf + c * 132 + w2 * 64 + ty * 8 +
                               t4 * 4) = v;
  }
  __syncthreads();

  if (tid < 192)
    smu[BIAS2f + tid] = pack_h2(smf[BIASf + 2 * tid + 1], smf[BIASf + 2 * tid]);

  // ---- LayerNorm -> f16 A tile
  {
    int tok = tid >> 2, cl2 = tid & 3;
    float v0a[24], v1a[24];
    float sum = 0.f, sq = 0.f;
    #pragma unroll
    for (int i = 0; i < 24; ++i) {
      int c = 8 * i + 2 * cl2;
      float v0 = smf[STAGEf + c * 132 + tok];
      float v1 = smf[STAGEf + (c + 1) * 132 + tok];
      v0a[i] = v0;
      v1a[i] = v1;
      sum += v0 + v1;
      sq += v0 * v0 + v1 * v1;
    }
    sum += __shfl_xor_sync(0xffffffffu, sum, 1);
    sq += __shfl_xor_sync(0xffffffffu, sq, 1);
    sum += __shfl_xor_sync(0xffffffffu, sum, 2);
    sq += __shfl_xor_sync(0xffffffffu, sq, 2);
    float mu = sum * (1.f / C_);
    float rstd = rsqrtf(sq * (1.f / C_) - mu * mu + 1e-5f);
    #pragma unroll
    for (int i = 0; i < 24; ++i) {
      int c = 8 * i + 2 * cl2;
      float xn0 = (v0a[i] - mu) * rstd * smf[GAMMAf + c] + smf[BETAf + c];
      float xn1 =
          (v1a[i] - mu) * rstd * smf[GAMMAf + c + 1] + smf[BETAf + c + 1];
      *reinterpret_cast<unsigned*>(smraw + OFF_ASH + tok * 400 + c * 2) =
          pack_h2(xn1, xn0);
    }
  }

  // ---- QK+vw GEMM: warp = (mt: 64 rows, nh: 7 n-tiles), ldmatrix + 2-stage
  {
    const int mt = wid & 1, nh = wid >> 1;
    const int ntBeg = nh * 7;  // n-tiles of 8 cols; valid ntg: 0..48
    unsigned acc[4][7][2];
    #pragma unroll
    for (int mi = 0; mi < 4; ++mi)
      #pragma unroll
      for (int nt = 0; nt < 7; ++nt) acc[mi][nt][0] = acc[mi][nt][1] = 0u;

    // per-lane ldmatrix base addresses
    const int arow = (lane & 7) + ((lane >> 3) & 1) * 8;
    const int akoff = (lane >> 4) * 16;
    unsigned aAddr[4];
    #pragma unroll
    for (int mi = 0; mi < 4; ++mi)
      aAddr[mi] =
          sbase + OFF_ASH + (mt * 64 + mi * 16 + arow) * 400 + akoff;
    const unsigned bAddrBase =
        ((ntBeg + (lane >> 4)) * 8 + (lane & 7)) * 48 + ((lane >> 3) & 1) * 16;
    const unsigned bAddr2 =
        ((ntBeg + 6) * 8 + (lane & 7)) * 48 + ((lane >> 3) & 1) * 16;

    #pragma unroll 1
    for (int kt = 0; kt < 12; ++kt) {
      CP_WAIT0();
      __syncthreads();
      if (kt < 11) {
        unsigned db = sbase + OFF_BCH + ((kt + 1) & 1) * CHUNKB;
        const uint4* src = g_wpack4 + (kt + 1) * 1344;
        for (int i = tid; i < 1344; i += 512) cpasync16(db + i * 16, src + i);
        CP_COMMIT();
      }
      unsigned Af[16];
      #pragma unroll
      for (int mi = 0; mi < 4; ++mi) ldsm4(Af + mi * 4, aAddr[mi] + kt * 32);
      const unsigned cb = sbase + OFF_BCH + (kt & 1) * CHUNKB;
      unsigned Bf[14];
      #pragma unroll
      for (int p = 0; p < 6; p += 2)
        if (ntBeg + p <= 48) ldsm4(Bf + p * 2, cb + bAddrBase + p * 384);
      if (ntBeg + 6 <= 48) ldsm2(Bf + 12, cb + bAddr2);
      #pragma unroll
      for (int nt = 0; nt < 7; ++nt) {
        if (ntBeg + nt <= 48) {
          #pragma unroll
          for (int mi = 0; mi < 4; ++mi)
            mma_h(acc[mi][nt], Af[mi * 4], Af[mi * 4 + 1], Af[mi * 4 + 2],
                  Af[mi * 4 + 3], Bf[nt * 2], Bf[nt * 2 + 1]);
        }
      }
    }

    // epilogue
    #pragma unroll
    for (int mi = 0; mi < 4; ++mi) {
      const int r0 = mt * 64 + mi * 16 + g;
      #pragma unroll
      for (int nt = 0; nt < 7; ++nt) {
        int ntg = ntBeg + nt;
        if (ntg < 48) {
          __half2 bp2 = *reinterpret_cast<__half2*>(smu + BIAS2f + ntg * 4 + t);
          __half2 p0 =
              __hadd2(*reinterpret_cast<__half2*>(&acc[mi][nt][0]), bp2);
          __half2 p1 =
              __hadd2(*reinterpret_cast<__half2*>(&acc[mi][nt][1]), bp2);
          int cbyte = (ntg * 8 + 2 * t) * 2;
          *reinterpret_cast<__half2*>(smraw + OFF_ARENA + r0 * 816 + cbyte) =
              p0;
          *reinterpret_cast<__half2*>(smraw + OFF_ARENA + (r0 + 8) * 816 +
                                      cbyte) = p1;
        } else if (ntg == 48) {
          float2 v0 =
              __half22float2(*reinterpret_cast<__half2*>(&acc[mi][nt][0]));
          float2 v1 =
              __half22float2(*reinterpret_cast<__half2*>(&acc[mi][nt][1]));
          int h0 = 2 * t;
          float bv0 = smf[BIASf + 384 + h0], bv1 = smf[BIASf + 385 + h0];
          smf[VWf + h0 * 132 + r0] = v0.x + bv0;
          smf[VWf + (h0 + 1) * 132 + r0] = v0.y + bv1;
          smf[VWf + h0 * 132 + r0 + 8] = v1.x + bv0;
          smf[VWf + (h0 + 1) * 132 + r0 + 8] = v1.y + bv1;
        }
      }
    }
  }
  __syncthreads();

  // ---- attention: warp = (window, head), ldmatrix + HMMA + frag softmax
  {
    const int h = wid & 7;
    const int rbase = (wid >> 3) * 64;
    const int kcol = 384 + h * 48;  // byte offset of k head
    unsigned kb[16], kb8[8];
    float2 vv[8];
    #pragma unroll
    for (int p = 0; p < 8; p += 2) {
      unsigned addr = sbase + OFF_ARENA +
                      (rbase + (p + (lane >> 4)) * 8 + (lane & 7)) * 816 +
                      kcol + ((lane >> 3) & 1) * 16;
      ldsm4(kb + p * 2, addr);
    }
    #pragma unroll
    for (int q = 0; q < 8; q += 4) {
      unsigned addr = sbase + OFF_ARENA +
                      (rbase + (q + (lane >> 3)) * 8 + (lane & 7)) * 816 +
                      kcol + 32;
      ldsm4(kb8 + q, addr);
    }
    #pragma unroll
    for (int nt = 0; nt < 8; ++nt)
      vv[nt] = *reinterpret_cast<const float2*>(smf + VWf + h * 132 + rbase +
                                                nt * 8 + t * 2);

    #pragma unroll
    for (int mt2 = 0; mt2 < 4; ++mt2) {
      unsigned qf[4], qa[2];
      {
        unsigned qaddr =
            sbase + OFF_ARENA +
            (rbase + mt2 * 16 + ((lane >> 3) & 1) * 8 + (lane & 7)) * 816 +
            h * 48 + (lane >> 4) * 16;
        ldsm4(qf, qaddr);
        unsigned qaddr2 = sbase + OFF_ARENA +
                          (rbase + mt2 * 16 + (lane & 15)) * 816 + h * 48 + 32;
        ldsm2(qa, qaddr2);
      }
      float acc[8][4];
      #pragma unroll
      for (int i = 0; i < 8; ++i)
        #pragma unroll
        for (int j = 0; j < 4; ++j) acc[i][j] = 0.f;
      #pragma unroll
      for (int nt = 0; nt < 8; ++nt) {
        mma16f(acc[nt], qf[0], qf[1], qf[2], qf[3], kb[nt * 2], kb[nt * 2 + 1]);
        mma8f(acc[nt], qa[0], qa[1], kb8[nt]);
      }
      float m0 = -1e30f, m1 = -1e30f;
      #pragma unroll
      for (int nt = 0; nt < 8; ++nt) {
        m0 = fmaxf(m0, fmaxf(acc[nt][0], acc[nt][1]));
        m1 = fmaxf(m1, fmaxf(acc[nt][2], acc[nt][3]));
      }
      m0 = fmaxf(m0, __shfl_xor_sync(0xffffffffu, m0, 1));
      m1 = fmaxf(m1, __shfl_xor_sync(0xffffffffu, m1, 1));
      m0 = fmaxf(m0, __shfl_xor_sync(0xffffffffu, m0, 2));
      m1 = fmaxf(m1, __shfl_xor_sync(0xffffffffu, m1, 2));
      float mc0 = m0 * CEXP_, mc1 = m1 * CEXP_;
      float sp0 = 0.f, sv0 = 0.f, sp1 = 0.f, sv1 = 0.f;
      #pragma unroll
      for (int nt = 0; nt < 8; ++nt) {
        float p00 = ex2a(fmaf(acc[nt][0], CEXP_, -mc0));
        float p01 = ex2a(fmaf(acc[nt][1], CEXP_, -mc0));
        float p10 = ex2a(fmaf(acc[nt][2], CEXP_, -mc1));
        float p11 = ex2a(fmaf(acc[nt][3], CEXP_, -mc1));
        sp0 += p00 + p01;
        sp1 += p10 + p11;
        sv0 = fmaf(p00, vv[nt].x, fmaf(p01, vv[nt].y, sv0));
        sv1 = fmaf(p10, vv[nt].x, fmaf(p11, vv[nt].y, sv1));
      }
      sp0 += __shfl_xor_sync(0xffffffffu, sp0, 1);
      sv0 += __shfl_xor_sync(0xffffffffu, sv0, 1);
      sp1 += __shfl_xor_sync(0xffffffffu, sp1, 1);
      sv1 += __shfl_xor_sync(0xffffffffu, sv1, 1);
      sp0 += __shfl_xor_sync(0xffffffffu, sp0, 2);
      sv0 += __shfl_xor_sync(0xffffffffu, sv0, 2);
      sp1 += __shfl_xor_sync(0xffffffffu, sp1, 2);
      sv1 += __shfl_xor_sync(0xffffffffu, sv1, 2);
      if (t == 0) {
        smf[OUTPf + wid * 64 + mt2 * 16 + g] = __fdividef(sv0, sp0);
        smf[OUTPf + wid * 64 + mt2 * 16 + g + 8] = __fdividef(sv1, sp1);
      }
    }
  }
  __syncthreads();

  // ---- final: sum 8 heads, sigmoid, store
  if (tid < 128) {
    int w2 = tid >> 6, row = tid & 63;
    float s = 0.f;
    #pragma unroll
    for (int h = 0; h < 8; ++h) s += smf[OUTPf + (w2 * 8 + h) * 64 + row];
    float v = s + g_bpmean;
    float sig = 1.f / (1.f + __expf(-v));
    out[(size_t)bN * 65536 + (wy * 8 + (row >> 3)) * 256 + (wx0 + w2) * 8 +
        (row & 7)] = sig;
  }
}

extern "C" void kernel_launch(void* const* d_in, const int* in_sizes, int n_in,
                              void* d_out, int out_size) {
  const float* x = (const float*)d_in[0];
  const float* gamma = (const float*)d_in[1];
  const float* beta = (const float*)d_in[2];
  const float* w_qkv = (const float*)d_in[3];
  const float* b_qkv = (const float*)d_in[4];
  const float* w_proj = (const float*)d_in[5];
  const float* b_proj = (const float*)d_in[6];
  float* out = (float*)d_out;

  cudaFuncSetAttribute(swin_mma_kernel,
                       cudaFuncAttributeMaxDynamicSharedMemorySize, SMEM_BYTES);

  pk_wps<<<C_, 32>>>(w_proj);
  pk_wv<<<7, 256>>>(w_qkv, b_qkv, b_proj);
  pk_pack<<<(129024 + 255) / 256, 256>>>(w_qkv);
  swin_mma_kernel<<<4096, 512, SMEM_BYTES>>>(x, gamma, beta, b_qkv, out);
}

// round 7
// speedup vs baseline: 6.0265x; 1.0727x over previous
#include <cuda_runtime.h>
#include <cuda_fp16.h>

#define C_ 192
#define NH_ 8
#define HD_ 24
#define CEXP_ 0.29448618f  // (HD^-0.5) * log2(e)

// ---- smem float-index offsets (low region) ----
#define BIASf 0      // 392 floats: b_qkv[384] | bveff[8]
#define BIAS2f 392   // 192 u32: f16x2 bias pairs
#define GAMMAf 584
#define BETAf 776
#define VWf 968      // [8][68] fp32
#define OUTPf 1512   // [8][64] fp32
// ---- byte offsets ----
#define OFF_ASH 8192      // f16 A [64 rows][200] stride 400B = 25600
#define OFF_BCH 33792     // 2 x B chunk [400 n][32B] = 2*12800
#define CHUNKB 12800
#define OFF_ARENA 59392   // f16 qk arena [64 rows][392] stride 784B = 50176
#define STAGEf 14848      // fp32 stage_c [192][68] (overlays arena) = 52224
#define SMEM_BYTES 111616

__device__ float g_wps[C_];
__device__ float g_wveff[C_ * NH_];
__device__ float g_bveff[NH_];
__device__ float g_bpmean;
__device__ uint4 g_wpack4[9600];  // [12 kt][400 n][32B] f16, swizzled

// ---------------- asm helpers ----------------
__device__ __forceinline__ unsigned smem_u32(const void* p) {
  unsigned a;
  asm("{ .reg .u64 t; cvta.to.shared.u64 t, %1; cvt.u32.u64 %0, t; }"
      : "=r"(a) : "l"(p));
  return a;
}
__device__ __forceinline__ void cpasync16(unsigned dst, const void* src) {
  asm volatile("cp.async.cg.shared.global [%0], [%1], 16;" :: "r"(dst),
               "l"(src));
}
#define CP_COMMIT() asm volatile("cp.async.commit_group;" ::: "memory")
#define CP_WAIT0() asm volatile("cp.async.wait_group 0;" ::: "memory")

__device__ __forceinline__ void ldsm4(unsigned* r, unsigned addr) {
  asm volatile("ldmatrix.sync.aligned.m8n8.x4.shared.b16 {%0,%1,%2,%3}, [%4];"
               : "=r"(r[0]), "=r"(r[1]), "=r"(r[2]), "=r"(r[3]) : "r"(addr));
}
__device__ __forceinline__ void ldsm2(unsigned* r, unsigned addr) {
  asm volatile("ldmatrix.sync.aligned.m8n8.x2.shared.b16 {%0,%1}, [%2];"
               : "=r"(r[0]), "=r"(r[1]) : "r"(addr));
}
__device__ __forceinline__ void mma_h(unsigned* c, unsigned a0, unsigned a1,
                                      unsigned a2, unsigned a3, unsigned b0,
                                      unsigned b1) {
  asm volatile(
      "mma.sync.aligned.m16n8k16.row.col.f16.f16.f16.f16 "
      "{%0,%1},{%2,%3,%4,%5},{%6,%7},{%0,%1};"
      : "+r"(c[0]), "+r"(c[1])
      : "r"(a0), "r"(a1), "r"(a2), "r"(a3), "r"(b0), "r"(b1));
}
__device__ __forceinline__ void mma16f(float* d, unsigned a0, unsigned a1,
                                       unsigned a2, unsigned a3, unsigned b0,
                                       unsigned b1) {
  asm volatile(
      "mma.sync.aligned.m16n8k16.row.col.f32.f16.f16.f32 "
      "{%0,%1,%2,%3},{%4,%5,%6,%7},{%8,%9},{%0,%1,%2,%3};"
      : "+f"(d[0]), "+f"(d[1]), "+f"(d[2]), "+f"(d[3])
      : "r"(a0), "r"(a1), "r"(a2), "r"(a3), "r"(b0), "r"(b1));
}
__device__ __forceinline__ void mma8f(float* d, unsigned a0, unsigned a1,
                                      unsigned b0) {
  asm volatile(
      "mma.sync.aligned.m16n8k8.row.col.f32.f16.f16.f32 "
      "{%0,%1,%2,%3},{%4,%5},{%6},{%0,%1,%2,%3};"
      : "+f"(d[0]), "+f"(d[1]), "+f"(d[2]), "+f"(d[3])
      : "r"(a0), "r"(a1), "r"(b0));
}
__device__ __forceinline__ float ex2a(float x) {
  float r;
  asm("ex2.approx.f32 %0, %1;" : "=f"(r) : "f"(x));
  return r;
}
__device__ __forceinline__ unsigned pack_h2(float hi, float lo) {
  unsigned r;
  asm("cvt.rn.f16x2.f32 %0, %1, %2;" : "=r"(r) : "f"(hi), "f"(lo));
  return r;
}

// ---------------- precompute ----------------
__global__ void pk_wps(const float* __restrict__ w_proj) {
  int k = blockIdx.x, l = threadIdx.x;
  float s = 0.f;
  for (int c = l; c < C_; c += 32) s += w_proj[k * C_ + c];
  #pragma unroll
  for (int o = 16; o > 0; o >>= 1) s += __shfl_xor_sync(0xffffffffu, s, o);
  if (l == 0) g_wps[k] = s * (1.f / C_);
}

__global__ void pk_wv(const float* __restrict__ w_qkv,
                      const float* __restrict__ b_qkv,
                      const float* __restrict__ b_proj) {
  int idx = blockIdx.x * 256 + threadIdx.x;
  if (idx < 1536) {
    int k = idx >> 3, h = idx & 7;
    float a = 0.f;
    for (int d = 0; d < HD_; ++d)
      a += w_qkv[k * 576 + 384 + h * HD_ + d] * g_wps[h * HD_ + d];
    g_wveff[idx] = a;
  } else if (idx < 1544) {
    int h = idx - 1536;
    float a = 0.f;
    for (int d = 0; d < HD_; ++d)
      a += b_qkv[384 + h * HD_ + d] * g_wps[h * HD_ + d];
    g_bveff[h] = a;
  } else if (idx == 1544) {
    float a = 0.f;
    for (int c = 0; c < C_; ++c) a += b_proj[c];
    g_bpmean = a * (1.f / C_);
  }
}

// pack [12 kt][400 n][32B]: byte = kt*12800 + n*32 + ((j>>3)^((n>>2)&1))*16 + (j&7)*2
__global__ void pk_pack(const float* __restrict__ w_qkv) {
  int idx = blockIdx.x * 256 + threadIdx.x;  // 12*400*16 = 76800
  if (idx >= 76800) return;
  int j = idx & 15;
  int n = (idx >> 4) % 400;
  int kt = idx / 6400;
  float v = 0.f;
  if (n < 392) {
    int k = kt * 16 + j;
    v = (n < 384) ? w_qkv[k * 576 + n] : g_wveff[k * 8 + (n - 384)];
  }
  int byte = kt * 12800 + n * 32 + (((j >> 3) ^ ((n >> 2) & 1)) << 4) +
             (j & 7) * 2;
  *reinterpret_cast<__half*>(reinterpret_cast<char*>(g_wpack4) + byte) =
      __float2half(v);
}

// ---------------- main fused kernel: 1 window / CTA, 256 threads ----------
__global__ __launch_bounds__(256, 2) void swin_mma_kernel(
    const float* __restrict__ x, const float* __restrict__ gamma,
    const float* __restrict__ beta, const float* __restrict__ b_qkv,
    float* __restrict__ out) {
  extern __shared__ unsigned char smraw[];
  float* smf = reinterpret_cast<float*>(smraw);
  unsigned* smu = reinterpret_cast<unsigned*>(smraw);
  const unsigned sbase = smem_u32(smraw);
  const int tid = threadIdx.x;
  const int wid = tid >> 5;
  const int lane = tid & 31;
  const int g = lane >> 2;
  const int t = lane & 3;

  const int win = blockIdx.x;
  const int bN = win >> 10;
  const int wy = (win >> 5) & 31;
  const int wx = win & 31;
  const float* xb = x + (size_t)bN * (C_ * 65536) + wy * 2048 + wx * 8;

  // prefetch B chunk 0 (overlaps x-load + LN)
  {
    unsigned db = sbase + OFF_BCH;
    for (int i = tid; i < 800; i += 256) cpasync16(db + i * 16, g_wpack4 + i);
    CP_COMMIT();
  }

  for (int i = tid; i < 392; i += 256)
    smf[BIASf + i] = (i < 384) ? b_qkv[i] : g_bveff[i - 384];
  if (tid < C_) {
    smf[GAMMAf + tid] = gamma[tid];
    smf[BETAf + tid] = beta[tid];
  }

  // ---- load x -> stage_c [c][68] fp32
  #pragma unroll
  for (int u = 0; u < 12; ++u) {
    int idx = tid + u * 256;   // 3072 float4
    int c = idx >> 4;
    int rem = idx & 15;
    int ty = rem >> 1, t4 = rem & 1;
    float4 v = *reinterpret_cast<const float4*>(xb + (size_t)c * 65536 +
                                                ty * 256 + t4 * 4);
    *reinterpret_cast<float4*>(smf + STAGEf + c * 68 + ty * 8 + t4 * 4) = v;
  }
  __syncthreads();

  if (tid < 192)
    smu[BIAS2f + tid] = pack_h2(smf[BIASf + 2 * tid + 1], smf[BIASf + 2 * tid]);

  // ---- LayerNorm -> f16 A tile [64][400B]
  {
    int tok = tid >> 2, cl2 = tid & 3;
    float v0a[24], v1a[24];
    float sum = 0.f, sq = 0.f;
    #pragma unroll
    for (int i = 0; i < 24; ++i) {
      int c = 8 * i + 2 * cl2;
      float v0 = smf[STAGEf + c * 68 + tok];
      float v1 = smf[STAGEf + (c + 1) * 68 + tok];
      v0a[i] = v0;
      v1a[i] = v1;
      sum += v0 + v1;
      sq += v0 * v0 + v1 * v1;
    }
    sum += __shfl_xor_sync(0xffffffffu, sum, 1);
    sq += __shfl_xor_sync(0xffffffffu, sq, 1);
    sum += __shfl_xor_sync(0xffffffffu, sum, 2);
    sq += __shfl_xor_sync(0xffffffffu, sq, 2);
    float mu = sum * (1.f / C_);
    float rstd = rsqrtf(sq * (1.f / C_) - mu * mu + 1e-5f);
    #pragma unroll
    for (int i = 0; i < 24; ++i) {
      int c = 8 * i + 2 * cl2;
      float xn0 = (v0a[i] - mu) * rstd * smf[GAMMAf + c] + smf[BETAf + c];
      float xn1 =
          (v1a[i] - mu) * rstd * smf[GAMMAf + c + 1] + smf[BETAf + c + 1];
      *reinterpret_cast<unsigned*>(smraw + OFF_ASH + tok * 400 + c * 2) =
          pack_h2(xn1, xn0);
    }
  }

  // ---- QK+vw GEMM: D[64][392] = A[64x192] * W; warp = (mt:2, nh:4)
  {
    const int mt = wid & 1, nh = wid >> 1;
    const int ntBeg = nh * 13;  // 8-col n-tiles; valid ntg 0..48
    unsigned acc[2][13][2];
    #pragma unroll
    for (int mi = 0; mi < 2; ++mi)
      #pragma unroll
      for (int nt = 0; nt < 13; ++nt) acc[mi][nt][0] = acc[mi][nt][1] = 0u;

    const int arow = (lane & 7) + ((lane >> 3) & 1) * 8;
    const int akoff = (lane >> 4) * 16;
    unsigned aAddr[2];
    #pragma unroll
    for (int mi = 0; mi < 2; ++mi)
      aAddr[mi] = sbase + OFF_ASH + (mt * 32 + mi * 16 + arow) * 400 + akoff;

    // B ldmatrix per-lane offsets (within chunk), swizzled layout
    const int bswz = ((lane >> 2) & 1) << 4;  // = ((n>>2)&1)<<4
    const int bkh = ((lane >> 3) & 1) << 4;
    unsigned bOff[7];
    #pragma unroll
    for (int pp = 0; pp < 6; ++pp) {
      int n = (ntBeg + pp * 2 + ((lane >> 4) & 1)) * 8 + (lane & 7);
      bOff[pp] = n * 32 + (bkh ^ bswz);
    }
    {
      int n = (ntBeg + 12) * 8 + (lane & 7);
      bOff[6] = n * 32 + (bkh ^ bswz);
    }

    #pragma unroll 1
    for (int kt = 0; kt < 12; ++kt) {
      CP_WAIT0();
      __syncthreads();
      if (kt < 11) {
        unsigned db = sbase + OFF_BCH + ((kt + 1) & 1) * CHUNKB;
        const uint4* src = g_wpack4 + (kt + 1) * 800;
        for (int i = tid; i < 800; i += 256) cpasync16(db + i * 16, src + i);
        CP_COMMIT();
      }
      unsigned Af[8];
      #pragma unroll
      for (int mi = 0; mi < 2; ++mi) ldsm4(Af + mi * 4, aAddr[mi] + kt * 32);
      const unsigned cb = sbase + OFF_BCH + (kt & 1) * CHUNKB;
      unsigned Bf[26];
      #pragma unroll
      for (int pp = 0; pp < 6; ++pp)
        if (ntBeg + pp * 2 + 1 <= 48) ldsm4(Bf + pp * 4, cb + bOff[pp]);
      if (ntBeg + 12 <= 48) ldsm2(Bf + 24, cb + bOff[6]);
      #pragma unroll
      for (int nt = 0; nt < 13; ++nt) {
        if (ntBeg + nt <= 48) {
          #pragma unroll
          for (int mi = 0; mi < 2; ++mi)
            mma_h(acc[mi][nt], Af[mi * 4], Af[mi * 4 + 1], Af[mi * 4 + 2],
                  Af[mi * 4 + 3], Bf[nt * 2], Bf[nt * 2 + 1]);
        }
      }
    }

    // epilogue -> arena f16 [64][784B] + vw fp32
    #pragma unroll
    for (int mi = 0; mi < 2; ++mi) {
      const int r0 = mt * 32 + mi * 16 + g;
      #pragma unroll
      for (int nt = 0; nt < 13; ++nt) {
        int ntg = ntBeg + nt;
        if (ntg < 48) {
          __half2 bp2 = *reinterpret_cast<__half2*>(smu + BIAS2f + ntg * 4 + t);
          __half2 p0 =
              __hadd2(*reinterpret_cast<__half2*>(&acc[mi][nt][0]), bp2);
          __half2 p1 =
              __hadd2(*reinterpret_cast<__half2*>(&acc[mi][nt][1]), bp2);
          int cbyte = (ntg * 8 + 2 * t) * 2;
          *reinterpret_cast<__half2*>(smraw + OFF_ARENA + r0 * 784 + cbyte) =
              p0;
          *reinterpret_cast<__half2*>(smraw + OFF_ARENA + (r0 + 8) * 784 +
                                      cbyte) = p1;
        } else if (ntg == 48) {
          float2 v0 =
              __half22float2(*reinterpret_cast<__half2*>(&acc[mi][nt][0]));
          float2 v1 =
              __half22float2(*reinterpret_cast<__half2*>(&acc[mi][nt][1]));
          int h0 = 2 * t;
          float bv0 = smf[BIASf + 384 + h0], bv1 = smf[BIASf + 385 + h0];
          smf[VWf + h0 * 68 + r0] = v0.x + bv0;
          smf[VWf + (h0 + 1) * 68 + r0] = v0.y + bv1;
          smf[VWf + h0 * 68 + r0 + 8] = v1.x + bv0;
          smf[VWf + (h0 + 1) * 68 + r0 + 8] = v1.y + bv1;
        }
      }
    }
  }
  __syncthreads();

  // ---- attention: warp = head, ldmatrix + HMMA + fragment softmax
  {
    const int h = wid;
    const int kcol = 384 + h * 48;  // byte offset of k head
    unsigned kb[16], kb8[8];
    float2 vv[8];
    #pragma unroll
    for (int p = 0; p < 8; p += 2) {
      unsigned addr = sbase + OFF_ARENA +
                      ((p + (lane >> 4)) * 8 + (lane & 7)) * 784 + kcol +
                      ((lane >> 3) & 1) * 16;
      ldsm4(kb + p * 2, addr);
    }
    #pragma unroll
    for (int q4 = 0; q4 < 8; q4 += 4) {
      unsigned addr = sbase + OFF_ARENA +
                      ((q4 + (lane >> 3)) * 8 + (lane & 7)) * 784 + kcol + 32;
      ldsm4(kb8 + q4, addr);
    }
    #pragma unroll
    for (int nt = 0; nt < 8; ++nt)
      vv[nt] =
          *reinterpret_cast<const float2*>(smf + VWf + h * 68 + nt * 8 + t * 2);

    #pragma unroll
    for (int mt2 = 0; mt2 < 4; ++mt2) {
      unsigned qf[4], qa[2];
      {
        unsigned qaddr = sbase + OFF_ARENA +
                         (mt2 * 16 + ((lane >> 3) & 1) * 8 + (lane & 7)) * 784 +
                         h * 48 + (lane >> 4) * 16;
        ldsm4(qf, qaddr);
        unsigned qaddr2 =
            sbase + OFF_ARENA + (mt2 * 16 + (lane & 15)) * 784 + h * 48 + 32;
        ldsm2(qa, qaddr2);
      }
      float acc[8][4];
      #pragma unroll
      for (int i = 0; i < 8; ++i)
        #pragma unroll
        for (int j = 0; j < 4; ++j) acc[i][j] = 0.f;
      #pragma unroll
      for (int nt = 0; nt < 8; ++nt) {
        mma16f(acc[nt], qf[0], qf[1], qf[2], qf[3], kb[nt * 2], kb[nt * 2 + 1]);
        mma8f(acc[nt], qa[0], qa[1], kb8[nt]);
      }
      float m0 = -1e30f, m1 = -1e30f;
      #pragma unroll
      for (int nt = 0; nt < 8; ++nt) {
        m0 = fmaxf(m0, fmaxf(acc[nt][0], acc[nt][1]));
        m1 = fmaxf(m1, fmaxf(acc[nt][2], acc[nt][3]));
      }
      m0 = fmaxf(m0, __shfl_xor_sync(0xffffffffu, m0, 1));
      m1 = fmaxf(m1, __shfl_xor_sync(0xffffffffu, m1, 1));
      m0 = fmaxf(m0, __shfl_xor_sync(0xffffffffu, m0, 2));
      m1 = fmaxf(m1, __shfl_xor_sync(0xffffffffu, m1, 2));
      float mc0 = m0 * CEXP_, mc1 = m1 * CEXP_;
      float sp0 = 0.f, sv0 = 0.f, sp1 = 0.f, sv1 = 0.f;
      #pragma unroll
      for (int nt = 0; nt < 8; ++nt) {
        float p00 = ex2a(fmaf(acc[nt][0], CEXP_, -mc0));
        float p01 = ex2a(fmaf(acc[nt][1], CEXP_, -mc0));
        float p10 = ex2a(fmaf(acc[nt][2], CEXP_, -mc1));
        float p11 = ex2a(fmaf(acc[nt][3], CEXP_, -mc1));
        sp0 += p00 + p01;
        sp1 += p10 + p11;
        sv0 = fmaf(p00, vv[nt].x, fmaf(p01, vv[nt].y, sv0));
        sv1 = fmaf(p10, vv[nt].x, fmaf(p11, vv[nt].y, sv1));
      }
      sp0 += __shfl_xor_sync(0xffffffffu, sp0, 1);
      sv0 += __shfl_xor_sync(0xffffffffu, sv0, 1);
      sp1 += __shfl_xor_sync(0xffffffffu, sp1, 1);
      sv1 += __shfl_xor_sync(0xffffffffu, sv1, 1);
      sp0 += __shfl_xor_sync(0xffffffffu, sp0, 2);
      sv0 += __shfl_xor_sync(0xffffffffu, sv0, 2);
      sp1 += __shfl_xor_sync(0xffffffffu, sp1, 2);
      sv1 += __shfl_xor_sync(0xffffffffu, sv1, 2);
      if (t == 0) {
        smf[OUTPf + h * 64 + mt2 * 16 + g] = __fdividef(sv0, sp0);
        smf[OUTPf + h * 64 + mt2 * 16 + g + 8] = __fdividef(sv1, sp1);
      }
    }
  }
  __syncthreads();

  // ---- final: sum 8 heads, sigmoid, store
  if (tid < 64) {
    float s = 0.f;
    #pragma unroll
    for (int h = 0; h < 8; ++h) s += smf[OUTPf + h * 64 + tid];
    float v = s + g_bpmean;
    float sig = 1.f / (1.f + __expf(-v));
    out[(size_t)bN * 65536 + (wy * 8 + (tid >> 3)) * 256 + wx * 8 +
        (tid & 7)] = sig;
  }
}

extern "C" void kernel_launch(void* const* d_in, const int* in_sizes, int n_in,
                              void* d_out, int out_size) {
  const float* x = (const float*)d_in[0];
  const float* gamma = (const float*)d_in[1];
  const float* beta = (const float*)d_in[2];
  const float* w_qkv = (const float*)d_in[3];
  const float* b_qkv = (const float*)d_in[4];
  const float* w_proj = (const float*)d_in[5];
  const float* b_proj = (const float*)d_in[6];
  float* out = (float*)d_out;

  cudaFuncSetAttribute(swin_mma_kernel,
                       cudaFuncAttributeMaxDynamicSharedMemorySize, SMEM_BYTES);

  pk_wps<<<C_, 32>>>(w_proj);
  pk_wv<<<7, 256>>>(w_qkv, b_qkv, b_proj);
  pk_pack<<<(76800 + 255) / 256, 256>>>(w_qkv);
  swin_mma_kernel<<<8192, 256, SMEM_BYTES>>>(x, gamma, beta, b_qkv, out);
}

// round 8
// speedup vs baseline: 8.4959x; 1.4098x over previous
#include <cuda_runtime.h>
#include <cuda_fp16.h>

#define C_ 192
#define NH_ 8
#define HD_ 24
#define CEXP_ 0.29448618f  // (HD^-0.5) * log2(e)

// ---- smem float-index offsets ----
#define BIASf 0      // 392 floats: b_qkv[384] | bveff[8]
#define BIAS2f 392   // 196 u32: f16x2 bias pairs (cols 0..391)
#define GAMMAf 588
#define BETAf 780
#define VWf 972      // [8][68] fp32
#define OUTPf 1516   // [8][64] fp32
// ---- byte offsets ----
#define OFF_ASH 8192  // f16 A [64 rows][200] stride 400B = 25600
#define STAGEf 8448   // fp32 stage_c [192][68] = 52224 B at byte 33792
#define SMEM_BYTES 86016

__device__ float g_wps[C_];
__device__ float g_wveff[C_ * NH_];
__device__ float g_bveff[NH_];
__device__ float g_bpmean;
// [12 kt][400 n][32B]; within 32B, k order: [0,1,8,9][2,3,10,11][4,5,12,13][6,7,14,15]
__device__ uint4 g_wpackB[9600];

// ---------------- asm helpers ----------------
__device__ __forceinline__ unsigned smem_u32(const void* p) {
  unsigned a;
  asm("{ .reg .u64 t; cvta.to.shared.u64 t, %1; cvt.u32.u64 %0, t; }"
      : "=r"(a) : "l"(p));
  return a;
}
__device__ __forceinline__ void ldsm4(unsigned* r, unsigned addr) {
  asm volatile("ldmatrix.sync.aligned.m8n8.x4.shared.b16 {%0,%1,%2,%3}, [%4];"
               : "=r"(r[0]), "=r"(r[1]), "=r"(r[2]), "=r"(r[3]) : "r"(addr));
}
__device__ __forceinline__ void mma_h(unsigned* c, unsigned a0, unsigned a1,
                                      unsigned a2, unsigned a3, unsigned b0,
                                      unsigned b1) {
  asm volatile(
      "mma.sync.aligned.m16n8k16.row.col.f16.f16.f16.f16 "
      "{%0,%1},{%2,%3,%4,%5},{%6,%7},{%0,%1};"
      : "+r"(c[0]), "+r"(c[1])
      : "r"(a0), "r"(a1), "r"(a2), "r"(a3), "r"(b0), "r"(b1));
}
__device__ __forceinline__ void mma16f(float* d, unsigned a0, unsigned a1,
                                       unsigned a2, unsigned a3, unsigned b0,
                                       unsigned b1) {
  asm volatile(
      "mma.sync.aligned.m16n8k16.row.col.f32.f16.f16.f32 "
      "{%0,%1,%2,%3},{%4,%5,%6,%7},{%8,%9},{%0,%1,%2,%3};"
      : "+f"(d[0]), "+f"(d[1]), "+f"(d[2]), "+f"(d[3])
      : "r"(a0), "r"(a1), "r"(a2), "r"(a3), "r"(b0), "r"(b1));
}
__device__ __forceinline__ void mma8f(float* d, unsigned a0, unsigned a1,
                                      unsigned b0) {
  asm volatile(
      "mma.sync.aligned.m16n8k8.row.col.f32.f16.f16.f32 "
      "{%0,%1,%2,%3},{%4,%5},{%6},{%0,%1,%2,%3};"
      : "+f"(d[0]), "+f"(d[1]), "+f"(d[2]), "+f"(d[3])
      : "r"(a0), "r"(a1), "r"(b0));
}
__device__ __forceinline__ float ex2a(float x) {
  float r;
  asm("ex2.approx.f32 %0, %1;" : "=f"(r) : "f"(x));
  return r;
}
__device__ __forceinline__ unsigned pack_h2(float hi, float lo) {
  unsigned r;
  asm("cvt.rn.f16x2.f32 %0, %1, %2;" : "=r"(r) : "f"(hi), "f"(lo));
  return r;
}

// ---------------- precompute ----------------
__global__ void pk_wps(const float* __restrict__ w_proj) {
  int k = blockIdx.x, l = threadIdx.x;
  float s = 0.f;
  for (int c = l; c < C_; c += 32) s += w_proj[k * C_ + c];
  #pragma unroll
  for (int o = 16; o > 0; o >>= 1) s += __shfl_xor_sync(0xffffffffu, s, o);
  if (l == 0) g_wps[k] = s * (1.f / C_);
}

__global__ void pk_wv(const float* __restrict__ w_qkv,
                      const float* __restrict__ b_qkv,
                      const float* __restrict__ b_proj) {
  int idx = blockIdx.x * 256 + threadIdx.x;
  if (idx < 1536) {
    int k = idx >> 3, h = idx & 7;
    float a = 0.f;
    for (int d = 0; d < HD_; ++d)
      a += w_qkv[k * 576 + 384 + h * HD_ + d] * g_wps[h * HD_ + d];
    g_wveff[idx] = a;
  } else if (idx < 1544) {
    int h = idx - 1536;
    float a = 0.f;
    for (int d = 0; d < HD_; ++d)
      a += b_qkv[384 + h * HD_ + d] * g_wps[h * HD_ + d];
    g_bveff[h] = a;
  } else if (idx == 1544) {
    float a = 0.f;
    for (int c = 0; c < C_; ++c) a += b_proj[c];
    g_bpmean = a * (1.f / C_);
  }
}

// pack: byte = kt*12800 + n*32 + ((k&7)>>1)*8 + ((k>>3)&1)*4 + (k&1)*2
__global__ void pk_pack(const float* __restrict__ w_qkv) {
  int idx = blockIdx.x * 256 + threadIdx.x;  // 12*400*16
  if (idx >= 76800) return;
  int k = idx & 15;
  int n = (idx >> 4) % 400;
  int kt = idx / 6400;
  float v = 0.f;
  if (n < 392) {
    int kf = kt * 16 + k;
    v = (n < 384) ? w_qkv[kf * 576 + n] : g_wveff[kf * 8 + (n - 384)];
  }
  int byte = kt * 12800 + n * 32 + (((k & 7) >> 1) << 3) + (((k >> 3) & 1) << 2) +
             ((k & 1) << 1);
  *reinterpret_cast<__half*>(reinterpret_cast<char*>(g_wpackB) + byte) =
      __float2half(v);
}

// ---------------- main fused kernel: 1 window / CTA, 256 threads ----------
__global__ __launch_bounds__(256, 2) void swin_reg_kernel(
    const float* __restrict__ x, const float* __restrict__ gamma,
    const float* __restrict__ beta, const float* __restrict__ b_qkv,
    float* __restrict__ out) {
  extern __shared__ unsigned char smraw[];
  float* smf = reinterpret_cast<float*>(smraw);
  unsigned* smu = reinterpret_cast<unsigned*>(smraw);
  const unsigned sbase = smem_u32(smraw);
  const int tid = threadIdx.x;
  const int h = tid >> 5;  // warp = head
  const int lane = tid & 31;
  const int g = lane >> 2;
  const int t = lane & 3;

  const int win = blockIdx.x;
  const int bN = win >> 10;
  const int wy = (win >> 5) & 31;
  const int wx = win & 31;
  const float* xb = x + (size_t)bN * (C_ * 65536) + wy * 2048 + wx * 8;

  for (int i = tid; i < 392; i += 256)
    smf[BIASf + i] = (i < 384) ? b_qkv[i] : g_bveff[i - 384];
  if (tid < C_) {
    smf[GAMMAf + tid] = gamma[tid];
    smf[BETAf + tid] = beta[tid];
  }

  // ---- load x -> stage_c [c][68] fp32
  #pragma unroll
  for (int u = 0; u < 12; ++u) {
    int idx = tid + u * 256;
    int c = idx >> 4;
    int rem = idx & 15;
    int ty = rem >> 1, t4 = rem & 1;
    float4 v = *reinterpret_cast<const float4*>(xb + (size_t)c * 65536 +
                                                ty * 256 + t4 * 4);
    *reinterpret_cast<float4*>(smf + STAGEf + c * 68 + ty * 8 + t4 * 4) = v;
  }
  __syncthreads();

  if (tid < 196)
    smu[BIAS2f + tid] = pack_h2(smf[BIASf + 2 * tid + 1], smf[BIASf + 2 * tid]);

  // ---- LayerNorm -> f16 A tile [64][400B]
  {
    int tok = tid >> 2, cl2 = tid & 3;
    float v0a[24], v1a[24];
    float sum = 0.f, sq = 0.f;
    #pragma unroll
    for (int i = 0; i < 24; ++i) {
      int c = 8 * i + 2 * cl2;
      float v0 = smf[STAGEf + c * 68 + tok];
      float v1 = smf[STAGEf + (c + 1) * 68 + tok];
      v0a[i] = v0;
      v1a[i] = v1;
      sum += v0 + v1;
      sq += v0 * v0 + v1 * v1;
    }
    sum += __shfl_xor_sync(0xffffffffu, sum, 1);
    sq += __shfl_xor_sync(0xffffffffu, sq, 1);
    sum += __shfl_xor_sync(0xffffffffu, sum, 2);
    sq += __shfl_xor_sync(0xffffffffu, sq, 2);
    float mu = sum * (1.f / C_);
    float rstd = rsqrtf(sq * (1.f / C_) - mu * mu + 1e-5f);
    #pragma unroll
    for (int i = 0; i < 24; ++i) {
      int c = 8 * i + 2 * cl2;
      float xn0 = (v0a[i] - mu) * rstd * smf[GAMMAf + c] + smf[BETAf + c];
      float xn1 =
          (v1a[i] - mu) * rstd * smf[GAMMAf + c + 1] + smf[BETAf + c + 1];
      *reinterpret_cast<unsigned*>(smraw + OFF_ASH + tok * 400 + c * 2) =
          pack_h2(xn1, xn0);
    }
  }
  __syncthreads();

  // ---- per-head GEMM, all in registers ----
  unsigned accq[4][3][2], acck[4][3][2], accv[4][2];
  #pragma unroll
  for (int mi = 0; mi < 4; ++mi) {
    #pragma unroll
    for (int j = 0; j < 3; ++j) {
      accq[mi][j][0] = accq[mi][j][1] = 0u;
      acck[mi][j][0] = acck[mi][j][1] = 0u;
    }
    accv[mi][0] = accv[mi][1] = 0u;
  }
  {
    const int arow = (lane & 7) + ((lane >> 3) & 1) * 8;
    const int akoff = (lane >> 4) * 16;
    unsigned aAddr[4];
    #pragma unroll
    for (int mi = 0; mi < 4; ++mi)
      aAddr[mi] = sbase + OFF_ASH + (mi * 16 + arow) * 400 + akoff;

    const char* bgl = reinterpret_cast<const char*>(g_wpackB);
    unsigned boff[7];
    #pragma unroll
    for (int j = 0; j < 7; ++j) {
      int ntg = (j < 3) ? (3 * h + j) : ((j < 6) ? (24 + 3 * h + j - 3) : 48);
      boff[j] = (unsigned)((ntg * 8 + g) * 32 + t * 8);
    }
    uint2 Bc[7], Bn[7];
    #pragma unroll
    for (int j = 0; j < 7; ++j)
      Bc[j] = *reinterpret_cast<const uint2*>(bgl + boff[j]);

    #pragma unroll
    for (int kt = 0; kt < 12; ++kt) {
      if (kt < 11) {
        const char* bp = bgl + (kt + 1) * 12800;
        #pragma unroll
        for (int j = 0; j < 7; ++j)
          Bn[j] = *reinterpret_cast<const uint2*>(bp + boff[j]);
      }
      unsigned Af[16];
      #pragma unroll
      for (int mi = 0; mi < 4; ++mi) ldsm4(Af + mi * 4, aAddr[mi] + kt * 32);
      #pragma unroll
      for (int mi = 0; mi < 4; ++mi) {
        #pragma unroll
        for (int j = 0; j < 3; ++j)
          mma_h(accq[mi][j], Af[mi * 4], Af[mi * 4 + 1], Af[mi * 4 + 2],
                Af[mi * 4 + 3], Bc[j].x, Bc[j].y);
        #pragma unroll
        for (int j = 0; j < 3; ++j)
          mma_h(acck[mi][j], Af[mi * 4], Af[mi * 4 + 1], Af[mi * 4 + 2],
                Af[mi * 4 + 3], Bc[3 + j].x, Bc[3 + j].y);
        mma_h(accv[mi], Af[mi * 4], Af[mi * 4 + 1], Af[mi * 4 + 2],
              Af[mi * 4 + 3], Bc[6].x, Bc[6].y);
      }
      #pragma unroll
      for (int j = 0; j < 7; ++j) Bc[j] = Bn[j];
    }
  }

  // ---- bias add (f16x2) on q, k ----
  #pragma unroll
  for (int j = 0; j < 3; ++j) {
    __half2 bq = *reinterpret_cast<__half2*>(smu + BIAS2f + (3 * h + j) * 4 + t);
    __half2 bk =
        *reinterpret_cast<__half2*>(smu + BIAS2f + 96 + (3 * h + j) * 4 + t);
    #pragma unroll
    for (int mi = 0; mi < 4; ++mi) {
      #pragma unroll
      for (int c = 0; c < 2; ++c) {
        __half2 q2 = __hadd2(*reinterpret_cast<__half2*>(&accq[mi][j][c]), bq);
        accq[mi][j][c] = *reinterpret_cast<unsigned*>(&q2);
        __half2 k2 = __hadd2(*reinterpret_cast<__half2*>(&acck[mi][j][c]), bk);
        acck[mi][j][c] = *reinterpret_cast<unsigned*>(&k2);
      }
    }
  }

  // ---- vw extract: col h of accv -> smem vw_h[64] ----
  {
    float vwb = smf[BIASf + 384 + h];
    if (t == (h >> 1)) {
      #pragma unroll
      for (int mi = 0; mi < 4; ++mi) {
        __half2 c0 = *reinterpret_cast<__half2*>(&accv[mi][0]);
        __half2 c1 = *reinterpret_cast<__half2*>(&accv[mi][1]);
        float v0 = (h & 1) ? __high2float(c0) : __low2float(c0);
        float v1 = (h & 1) ? __high2float(c1) : __low2float(c1);
        smf[VWf + h * 68 + mi * 16 + g] = v0 + vwb;
        smf[VWf + h * 68 + mi * 16 + 8 + g] = v1 + vwb;
      }
    }
    __syncwarp();
  }
  float2 vv[8];
  #pragma unroll
  for (int kb = 0; kb < 8; ++kb)
    vv[kb] =
        *reinterpret_cast<const float2*>(smf + VWf + h * 68 + kb * 8 + t * 2);

  // ---- attention: logits from acc fragments directly, softmax, out ----
  #pragma unroll
  for (int mt2 = 0; mt2 < 4; ++mt2) {
    float acc[8][4];
    #pragma unroll
    for (int i = 0; i < 8; ++i)
      #pragma unroll
      for (int j = 0; j < 4; ++j) acc[i][j] = 0.f;
    #pragma unroll
    for (int kb = 0; kb < 8; ++kb) {
      mma16f(acc[kb], accq[mt2][0][0], accq[mt2][0][1], accq[mt2][1][0],
             accq[mt2][1][1], acck[kb >> 1][0][kb & 1], acck[kb >> 1][1][kb & 1]);
      mma8f(acc[kb], accq[mt2][2][0], accq[mt2][2][1],
            acck[kb >> 1][2][kb & 1]);
    }
    float m0 = -1e30f, m1 = -1e30f;
    #pragma unroll
    for (int kb = 0; kb < 8; ++kb) {
      m0 = fmaxf(m0, fmaxf(acc[kb][0], acc[kb][1]));
      m1 = fmaxf(m1, fmaxf(acc[kb][2], acc[kb][3]));
    }
    m0 = fmaxf(m0, __shfl_xor_sync(0xffffffffu, m0, 1));
    m1 = fmaxf(m1, __shfl_xor_sync(0xffffffffu, m1, 1));
    m0 = fmaxf(m0, __shfl_xor_sync(0xffffffffu, m0, 2));
    m1 = fmaxf(m1, __shfl_xor_sync(0xffffffffu, m1, 2));
    float mc0 = m0 * CEXP_, mc1 = m1 * CEXP_;
    float sp0 = 0.f, sv0 = 0.f, sp1 = 0.f, sv1 = 0.f;
    #pragma unroll
    for (int kb = 0; kb < 8; ++kb) {
      float p00 = ex2a(fmaf(acc[kb][0], CEXP_, -mc0));
      float p01 = ex2a(fmaf(acc[kb][1], CEXP_, -mc0));
      float p10 = ex2a(fmaf(acc[kb][2], CEXP_, -mc1));
      float p11 = ex2a(fmaf(acc[kb][3], CEXP_, -mc1));
      sp0 += p00 + p01;
      sp1 += p10 + p11;
      sv0 = fmaf(p00, vv[kb].x, fmaf(p01, vv[kb].y, sv0));
      sv1 = fmaf(p10, vv[kb].x, fmaf(p11, vv[kb].y, sv1));
    }
    sp0 += __shfl_xor_sync(0xffffffffu, sp0, 1);
    sv0 += __shfl_xor_sync(0xffffffffu, sv0, 1);
    sp1 += __shfl_xor_sync(0xffffffffu, sp1, 1);
    sv1 += __shfl_xor_sync(0xffffffffu, sv1, 1);
    sp0 += __shfl_xor_sync(0xffffffffu, sp0, 2);
    sv0 += __shfl_xor_sync(0xffffffffu, sv0, 2);
    sp1 += __shfl_xor_sync(0xffffffffu, sp1, 2);
    sv1 += __shfl_xor_sync(0xffffffffu, sv1, 2);
    if (t == 0) {
      smf[OUTPf + h * 64 + mt2 * 16 + g] = __fdividef(sv0, sp0);
      smf[OUTPf + h * 64 + mt2 * 16 + g + 8] = __fdividef(sv1, sp1);
    }
  }
  __syncthreads();

  // ---- final: sum 8 heads, sigmoid, store
  if (tid < 64) {
    float s = 0.f;
    #pragma unroll
    for (int hh = 0; hh < 8; ++hh) s += smf[OUTPf + hh * 64 + tid];
    float v = s + g_bpmean;
    float sig = 1.f / (1.f + __expf(-v));
    out[(size_t)bN * 65536 + (wy * 8 + (tid >> 3)) * 256 + wx * 8 +
        (tid & 7)] = sig;
  }
}

extern "C" void kernel_launch(void* const* d_in, const int* in_sizes, int n_in,
                              void* d_out, int out_size) {
  const float* x = (const float*)d_in[0];
  const float* gamma = (const float*)d_in[1];
  const float* beta = (const float*)d_in[2];
  const float* w_qkv = (const float*)d_in[3];
  const float* b_qkv = (const float*)d_in[4];
  const float* w_proj = (const float*)d_in[5];
  const float* b_proj = (const float*)d_in[6];
  float* out = (float*)d_out;

  cudaFuncSetAttribute(swin_reg_kernel,
                       cudaFuncAttributeMaxDynamicSharedMemorySize, SMEM_BYTES);

  pk_wps<<<C_, 32>>>(w_proj);
  pk_wv<<<7, 256>>>(w_qkv, b_qkv, b_proj);
  pk_pack<<<(76800 + 255) / 256, 256>>>(w_qkv);
  swin_reg_kernel<<<8192, 256, SMEM_BYTES>>>(x, gamma, beta, b_qkv, out);
}